// round 14
// baseline (speedup 1.0000x reference)
#include <cuda_runtime.h>
#include <cuda_bf16.h>
#include <mma.h>
#include <math.h>

using namespace nvcuda;

#define N_CFG 400000
#define E_CFG 1600000
#define N_FUNC 8000
#define N_FCG 9600
#define E_FCG 80000
#define NB 8
#define D_H 128
#define VOCAB 10002
#define FULLMASK 0xffffffffu

// ---------------- scratch (device globals) ----------------------------------
__device__ float g_b [(size_t)N_CFG * D_H];           // reused as bf16 HB2 (GEMM2 out)
__device__ __nv_bfloat16 g_hb[(size_t)N_CFG * D_H];   // GEMM1 out / gather2 src
__device__ __nv_bfloat16 g_wb1[64 * 128];
__device__ __nv_bfloat16 g_wb2[128 * 128];
__device__ int   g_deg[N_CFG];
__device__ float g_dis[N_CFG];
__device__ int   g_rowptr[N_CFG];
__device__ int   g_cursor[N_CFG];
__device__ int   g_csr[E_CFG];
__device__ int   g_fdeg[N_FCG];
__device__ float g_fdis[N_FCG];
__device__ int   g_frowptr[N_FCG];
__device__ int   g_fcursor[N_FCG];
__device__ int   g_fcsr[E_FCG];
__device__ int   g_bsum[512];
__device__ int   g_fstart[N_FUNC + 1];
__device__ int   g_bstart[NB + 1];
__device__ float g_pool[N_FUNC * D_H];
__device__ float g_fx [N_FCG * D_H];
__device__ float g_fz [N_FCG * D_H];
__device__ float g_fy [N_FCG * D_H];
__device__ float g_g  [NB * D_H];

#define NBLK_CFG ((N_CFG + 1023) / 1024)   // 391
#define NBLK_FCG ((N_FCG + 1023) / 1024)   // 10
#define FBSUM 400

static __device__ __forceinline__ unsigned pack_bf2(float a, float b) {
    __nv_bfloat162 h = __float22bfloat162_rn(make_float2(a, b));
    return *reinterpret_cast<unsigned*>(&h);
}
static __device__ __forceinline__ float2 unpack_bf2(unsigned u) {
    return __bfloat1622float2(*reinterpret_cast<const __nv_bfloat162*>(&u));
}

// ---------------- init: zero degs + weight->bf16 ------------------------------
__global__ void init_kernel(const float* __restrict__ W1, const float* __restrict__ W2) {
    int i = blockIdx.x * blockDim.x + threadIdx.x;
    if (i < N_CFG) g_deg[i] = 0;
    if (i < N_FCG) g_fdeg[i] = 0;
    if (i < 64 * 128) g_wb1[i] = __float2bfloat16(W1[i]);
    if (i >= 64 * 128 && i < 64 * 128 + 128 * 128)
        g_wb2[i - 64 * 128] = __float2bfloat16(W2[i - 64 * 128]);
}
__global__ void deg_all_kernel(const int* __restrict__ cei, const int* __restrict__ fei) {
    int i = blockIdx.x * blockDim.x + threadIdx.x;
    if (i < E_CFG) {
        atomicAdd(&g_deg[cei[E_CFG + i]], 1);
    } else if (i < E_CFG + E_FCG) {
        atomicAdd(&g_fdeg[fei[E_FCG + (i - E_CFG)]], 1);
    }
}

// ---------------- CSR build (merged; dis fused) -------------------------------
__device__ __forceinline__ void scan_local_body(const int* cnt, int n, int* out,
                                                int* bsum, float* dis, int blk, int t) {
    __shared__ int s[256];
    int base = blk * 1024;
    int v[4], sum = 0;
#pragma unroll
    for (int j = 0; j < 4; j++) {
        int i = base + t * 4 + j;
        v[j] = (i < n) ? cnt[i] : 0;
        if (i < n) dis[i] = rsqrtf((float)v[j] + 1.0f);
        sum += v[j];
    }
    s[t] = sum;
    __syncthreads();
    for (int off = 1; off < 256; off <<= 1) {
        int x = (t >= off) ? s[t - off] : 0;
        __syncthreads();
        s[t] += x;
        __syncthreads();
    }
    if (t == 255) bsum[blk] = s[255];
    int run = (t > 0) ? s[t - 1] : 0;
#pragma unroll
    for (int j = 0; j < 4; j++) {
        int i = base + t * 4 + j;
        if (i < n) out[i] = run;
        run += v[j];
    }
}
__global__ void scan_local_all() {
    if (blockIdx.x < NBLK_CFG)
        scan_local_body(g_deg, N_CFG, g_rowptr, g_bsum, g_dis, blockIdx.x, threadIdx.x);
    else
        scan_local_body(g_fdeg, N_FCG, g_frowptr, g_bsum + FBSUM, g_fdis,
                        blockIdx.x - NBLK_CFG, threadIdx.x);
}
__global__ void scan_bsum_all() {
    __shared__ int s[512];
    int* bsum = (blockIdx.x == 0) ? g_bsum : g_bsum + FBSUM;
    int nb = (blockIdx.x == 0) ? NBLK_CFG : NBLK_FCG;
    int t = threadIdx.x;
    s[t] = (t < nb) ? bsum[t] : 0;
    __syncthreads();
    for (int off = 1; off < 512; off <<= 1) {
        int x = (t >= off) ? s[t - off] : 0;
        __syncthreads();
        s[t] += x;
        __syncthreads();
    }
    if (t < nb) bsum[t] = (t > 0) ? s[t - 1] : 0;
}
__global__ void scan_add_all(const int* __restrict__ n2f, const int* __restrict__ fbatch) {
    int i = blockIdx.x * blockDim.x + threadIdx.x;
    if (i < N_CFG) {
        int v = g_rowptr[i] + g_bsum[i >> 10];
        g_rowptr[i] = v;
        g_cursor[i] = v;
    } else if (i < N_CFG + N_FCG) {
        int j = i - N_CFG;
        int v = g_frowptr[j] + g_bsum[FBSUM + (j >> 10)];
        g_frowptr[j] = v;
        g_fcursor[j] = v;
    } else if (i <= N_CFG + N_FCG + N_FUNC) {
        int f = i - (N_CFG + N_FCG);
        int lo = 0, hi = N_CFG;
        while (lo < hi) {
            int mid = (lo + hi) >> 1;
            if (n2f[mid] < f) lo = mid + 1; else hi = mid;
        }
        g_fstart[f] = lo;
    } else if (i <= N_CFG + N_FCG + N_FUNC + 1 + NB) {
        int f = i - (N_CFG + N_FCG + N_FUNC + 1);
        int lo = 0, hi = N_FCG;
        while (lo < hi) {
            int mid = (lo + hi) >> 1;
            if (fbatch[mid] < f) lo = mid + 1; else hi = mid;
        }
        g_bstart[f] = lo;
    }
}
__global__ void fill_csr_all(const int* __restrict__ cei, const int* __restrict__ fei) {
    int i = blockIdx.x * blockDim.x + threadIdx.x;
    if (i < E_CFG) {
        int r = cei[i], c = cei[E_CFG + i];
        int slot = atomicAdd(&g_cursor[c], 1);
        g_csr[slot] = r;
    } else if (i < E_CFG + E_FCG) {
        int j = i - E_CFG;
        int r = fei[j], c = fei[E_FCG + j];
        int slot = atomicAdd(&g_fcursor[c], 1);
        g_fcsr[slot] = r;
    }
}

// ---------------- FUSED gather + WMMA GEMM ------------------------------------
// Stage A by gathering neighbor rows directly into smem (quarter-warp per node),
// then run the bf16 WMMA K-loop entirely from smem.
// SRC_FP32: Xsrc is fp32 [N,64] (layer 1, dis folded per edge); else bf16 [N,128].
// Epilogue: relu(acc + bias) [*dis] -> bf16 row to HBout.
template<int K, bool SCALE, bool SRC_FP32>
__global__ __launch_bounds__(256) void gemmfused_kernel(
    const void* __restrict__ Xsrc,
    const int* __restrict__ rowptr, const int* __restrict__ deg,
    const int* __restrict__ csr,
    const __nv_bfloat16* __restrict__ Wb, const float* __restrict__ bias,
    const float* __restrict__ dis, __nv_bfloat16* __restrict__ HBout, int N) {
    constexpr int AP = K + 8;     // As pitch (bf16 elems)
    constexpr int WP = 136;
    extern __shared__ char smem[];
    __nv_bfloat16* As = (__nv_bfloat16*)smem;                          // 128*AP
    __nv_bfloat16* Ws = (__nv_bfloat16*)(smem + 128 * AP * 2);         // 32*WP
    float* Eb = (float*)(smem + 128 * AP * 2 + 32 * WP * 2);           // 8*320
    float* Bs = Eb + 8 * 320;                                          // 128

    const int tid = threadIdx.x;
    const int warp = tid >> 5, lane = tid & 31;
    const int q = lane >> 3, sub = lane & 7;
    const int row0 = blockIdx.x * 128;

    if (tid < 128) Bs[tid] = bias[tid];

    // ---- gather phase: 8 warps x 4 nodes x 4 iters = 128 rows ----
    for (int it = 0; it < 4; it++) {
        int r = it * 32 + warp * 4 + q;
        int node = row0 + r;
        int start = rowptr[node], d = deg[node];
        int dm = min(d, 8);
        int uidx = (sub < dm) ? csr[start + sub] : 0;
        int u[8];
#pragma unroll
        for (int j = 0; j < 8; j++) u[j] = __shfl_sync(FULLMASK, uidx, (q << 3) + j);
        float dn = dis[node];
        if (SRC_FP32) {
            const float4* x = (const float4*)Xsrc;    // rows of 16 float4
            float a[8];
            {
                float4 s0 = x[(size_t)node * 16 + sub * 2];
                float4 s1 = x[(size_t)node * 16 + sub * 2 + 1];
                a[0] = s0.x * dn; a[1] = s0.y * dn; a[2] = s0.z * dn; a[3] = s0.w * dn;
                a[4] = s1.x * dn; a[5] = s1.y * dn; a[6] = s1.z * dn; a[7] = s1.w * dn;
            }
#pragma unroll
            for (int j = 0; j < 8; j++) {
                if (j < dm) {
                    float du = dis[u[j]];
                    float4 r0 = x[(size_t)u[j] * 16 + sub * 2];
                    float4 r1 = x[(size_t)u[j] * 16 + sub * 2 + 1];
                    a[0] += r0.x * du; a[1] += r0.y * du; a[2] += r0.z * du; a[3] += r0.w * du;
                    a[4] += r1.x * du; a[5] += r1.y * du; a[6] += r1.z * du; a[7] += r1.w * du;
                }
            }
            for (int e = 8; e < d; e++) {
                int uu = csr[start + e];
                float du = dis[uu];
                float4 r0 = x[(size_t)uu * 16 + sub * 2];
                float4 r1 = x[(size_t)uu * 16 + sub * 2 + 1];
                a[0] += r0.x * du; a[1] += r0.y * du; a[2] += r0.z * du; a[3] += r0.w * du;
                a[4] += r1.x * du; a[5] += r1.y * du; a[6] += r1.z * du; a[7] += r1.w * du;
            }
            uint4 pk;
            pk.x = pack_bf2(a[0] * dn, a[1] * dn);
            pk.y = pack_bf2(a[2] * dn, a[3] * dn);
            pk.z = pack_bf2(a[4] * dn, a[5] * dn);
            pk.w = pack_bf2(a[6] * dn, a[7] * dn);
            *(uint4*)&As[r * AP + sub * 8] = pk;
        } else {
            const uint4* h16 = (const uint4*)Xsrc;    // rows of 16 uint4
            float acc[16];
            {
                uint4 r0 = h16[(size_t)node * 16 + sub];
                uint4 r1 = h16[(size_t)node * 16 + 8 + sub];
                float2 f0 = unpack_bf2(r0.x), f1 = unpack_bf2(r0.y);
                float2 f2 = unpack_bf2(r0.z), f3 = unpack_bf2(r0.w);
                float2 g0 = unpack_bf2(r1.x), g1 = unpack_bf2(r1.y);
                float2 g2 = unpack_bf2(r1.z), g3 = unpack_bf2(r1.w);
                acc[0] = f0.x;  acc[1] = f0.y;  acc[2] = f1.x;  acc[3] = f1.y;
                acc[4] = f2.x;  acc[5] = f2.y;  acc[6] = f3.x;  acc[7] = f3.y;
                acc[8] = g0.x;  acc[9] = g0.y;  acc[10] = g1.x; acc[11] = g1.y;
                acc[12] = g2.x; acc[13] = g2.y; acc[14] = g3.x; acc[15] = g3.y;
            }
#pragma unroll
            for (int j = 0; j < 8; j++) {
                if (j < dm) {
                    uint4 r0 = h16[(size_t)u[j] * 16 + sub];
                    uint4 r1 = h16[(size_t)u[j] * 16 + 8 + sub];
                    float2 f0 = unpack_bf2(r0.x), f1 = unpack_bf2(r0.y);
                    float2 f2 = unpack_bf2(r0.z), f3 = unpack_bf2(r0.w);
                    float2 g0 = unpack_bf2(r1.x), g1 = unpack_bf2(r1.y);
                    float2 g2 = unpack_bf2(r1.z), g3 = unpack_bf2(r1.w);
                    acc[0] += f0.x;  acc[1] += f0.y;  acc[2] += f1.x;  acc[3] += f1.y;
                    acc[4] += f2.x;  acc[5] += f2.y;  acc[6] += f3.x;  acc[7] += f3.y;
                    acc[8] += g0.x;  acc[9] += g0.y;  acc[10] += g1.x; acc[11] += g1.y;
                    acc[12] += g2.x; acc[13] += g2.y; acc[14] += g3.x; acc[15] += g3.y;
                }
            }
            for (int e = 8; e < d; e++) {
                int uu = csr[start + e];
                uint4 r0 = h16[(size_t)uu * 16 + sub];
                uint4 r1 = h16[(size_t)uu * 16 + 8 + sub];
                float2 f0 = unpack_bf2(r0.x), f1 = unpack_bf2(r0.y);
                float2 f2 = unpack_bf2(r0.z), f3 = unpack_bf2(r0.w);
                float2 g0 = unpack_bf2(r1.x), g1 = unpack_bf2(r1.y);
                float2 g2 = unpack_bf2(r1.z), g3 = unpack_bf2(r1.w);
                acc[0] += f0.x;  acc[1] += f0.y;  acc[2] += f1.x;  acc[3] += f1.y;
                acc[4] += f2.x;  acc[5] += f2.y;  acc[6] += f3.x;  acc[7] += f3.y;
                acc[8] += g0.x;  acc[9] += g0.y;  acc[10] += g1.x; acc[11] += g1.y;
                acc[12] += g2.x; acc[13] += g2.y; acc[14] += g3.x; acc[15] += g3.y;
            }
            uint4 pk0, pk1;
            pk0.x = pack_bf2(acc[0] * dn, acc[1] * dn);
            pk0.y = pack_bf2(acc[2] * dn, acc[3] * dn);
            pk0.z = pack_bf2(acc[4] * dn, acc[5] * dn);
            pk0.w = pack_bf2(acc[6] * dn, acc[7] * dn);
            pk1.x = pack_bf2(acc[8] * dn, acc[9] * dn);
            pk1.y = pack_bf2(acc[10] * dn, acc[11] * dn);
            pk1.z = pack_bf2(acc[12] * dn, acc[13] * dn);
            pk1.w = pack_bf2(acc[14] * dn, acc[15] * dn);
            *(uint4*)&As[r * AP + sub * 16]     = pk0;
            *(uint4*)&As[r * AP + sub * 16 + 8] = pk1;
        }
    }
    __syncthreads();

    // ---- WMMA K-loop from smem As ----
    const int wr = warp >> 2;
    const int wc = warp & 3;
    wmma::fragment<wmma::accumulator, 16, 16, 16, float> acc[4][2];
#pragma unroll
    for (int i = 0; i < 4; i++)
#pragma unroll
        for (int j = 0; j < 2; j++) wmma::fill_fragment(acc[i][j], 0.0f);

    const unsigned* Wu = (const unsigned*)Wb;
    unsigned* Wsu = (unsigned*)Ws;

    for (int kc = 0; kc < K; kc += 32) {
#pragma unroll
        for (int i = tid; i < 32 * 64; i += 256) {
            int k = i >> 6, c2 = i & 63;
            Wsu[k * (WP / 2) + c2] = Wu[(size_t)(kc + k) * 64 + c2];
        }
        __syncthreads();
#pragma unroll
        for (int ks = 0; ks < 32; ks += 16) {
            wmma::fragment<wmma::matrix_a, 16, 16, 16, __nv_bfloat16, wmma::row_major> af[4];
            wmma::fragment<wmma::matrix_b, 16, 16, 16, __nv_bfloat16, wmma::row_major> bf[2];
#pragma unroll
            for (int i = 0; i < 4; i++)
                wmma::load_matrix_sync(af[i], &As[(wr * 64 + i * 16) * AP + kc + ks], AP);
#pragma unroll
            for (int j = 0; j < 2; j++)
                wmma::load_matrix_sync(bf[j], &Ws[ks * WP + wc * 32 + j * 16], WP);
#pragma unroll
            for (int i = 0; i < 4; i++)
#pragma unroll
                for (int j = 0; j < 2; j++)
                    wmma::mma_sync(acc[i][j], af[i], bf[j], acc[i][j]);
        }
        __syncthreads();
    }

    // ---- epilogue ----
    const int r = lane >> 1, c8 = (lane & 1) * 8;
    float* myEb = Eb + warp * 320;
#pragma unroll
    for (int i = 0; i < 4; i++) {
#pragma unroll
        for (int j = 0; j < 2; j++) {
            wmma::store_matrix_sync(myEb, acc[i][j], 20, wmma::mem_row_major);
            __syncwarp();
            int gr = row0 + wr * 64 + i * 16 + r;
            int gc = wc * 32 + j * 16 + c8;
            float s = SCALE ? dis[gr] : 1.0f;
            float o[8];
#pragma unroll
            for (int qq = 0; qq < 8; qq++)
                o[qq] = fmaxf(myEb[r * 20 + c8 + qq] + Bs[gc + qq], 0.0f) * s;
            uint4 pk;
            pk.x = pack_bf2(o[0], o[1]); pk.y = pack_bf2(o[2], o[3]);
            pk.z = pack_bf2(o[4], o[5]); pk.w = pack_bf2(o[6], o[7]);
            *(uint4*)&HBout[(size_t)gr * 128 + gc] = pk;
            __syncwarp();
        }
    }
}

// ---------------- FFMA2 GEMM (fp32, FCG) --------------------------------------
template<int K, bool SCALE>
__global__ __launch_bounds__(256, 2) void gemmx_kernel(
    const float* __restrict__ X, const float* __restrict__ W,
    const float* __restrict__ bias, const float* __restrict__ dis,
    float* __restrict__ H, int N) {
    __shared__ float Xs[32 * 132];
    __shared__ float Ws[32 * 128];
    const int row0 = blockIdx.x * 128;
    const int tx = threadIdx.x & 15;
    const int ty = threadIdx.x >> 4;
    const int c0 = tx * 8, r0 = ty * 8;

    unsigned long long acc2[8][4];
#pragma unroll
    for (int r = 0; r < 8; r++)
#pragma unroll
        for (int j = 0; j < 4; j++) acc2[r][j] = 0ULL;

    for (int kc = 0; kc < K; kc += 32) {
#pragma unroll
        for (int i = threadIdx.x; i < 128 * 32; i += 256) {
            int k = i & 31, r = i >> 5;
            int gr = row0 + r;
            Xs[k * 132 + r] = (gr < N) ? X[(size_t)gr * K + kc + k] : 0.f;
        }
#pragma unroll
        for (int i = threadIdx.x; i < 32 * 128; i += 256) {
            int c = i & 127, k = i >> 7;
            Ws[k * 128 + c] = W[(size_t)(kc + k) * 128 + c];
        }
        __syncthreads();
#pragma unroll 4
        for (int k = 0; k < 32; k++) {
            float4 al = *(const float4*)&Xs[k * 132 + r0];
            float4 ah = *(const float4*)&Xs[k * 132 + r0 + 4];
            ulonglong2 wl = *(const ulonglong2*)&Ws[k * 128 + c0];
            ulonglong2 wh = *(const ulonglong2*)&Ws[k * 128 + c0 + 4];
            unsigned long long w2[4];
            w2[0] = wl.x; w2[1] = wl.y; w2[2] = wh.x; w2[3] = wh.y;
            float a[8];
            a[0] = al.x; a[1] = al.y; a[2] = al.z; a[3] = al.w;
            a[4] = ah.x; a[5] = ah.y; a[6] = ah.z; a[7] = ah.w;
#pragma unroll
            for (int r = 0; r < 8; r++) {
                unsigned long long a2;
                asm("mov.b64 %0, {%1, %1};" : "=l"(a2) : "f"(a[r]));
#pragma unroll
                for (int j = 0; j < 4; j++)
                    asm("fma.rn.f32x2 %0, %1, %2, %0;"
                        : "+l"(acc2[r][j]) : "l"(a2), "l"(w2[j]));
            }
        }
        __syncthreads();
    }

    float bb[8];
#pragma unroll
    for (int j = 0; j < 8; j++) bb[j] = bias[c0 + j];
#pragma unroll
    for (int r = 0; r < 8; r++) {
        int gr = row0 + r0 + r;
        if (gr >= N) return;
        float s = SCALE ? dis[gr] : 1.0f;
        float o[8];
#pragma unroll
        for (int j = 0; j < 4; j++) {
            float lo, hi;
            asm("mov.b64 {%0, %1}, %2;" : "=f"(lo), "=f"(hi) : "l"(acc2[r][j]));
            o[2 * j]     = fmaxf(lo + bb[2 * j], 0.f) * s;
            o[2 * j + 1] = fmaxf(hi + bb[2 * j + 1], 0.f) * s;
        }
        *(float4*)&H[(size_t)gr * 128 + c0]     = make_float4(o[0], o[1], o[2], o[3]);
        *(float4*)&H[(size_t)gr * 128 + c0 + 4] = make_float4(o[4], o[5], o[6], o[7]);
    }
}

// ---------------- gather 128ch fp32 (FCG), shuffle indices -------------------
__global__ __launch_bounds__(256) void gather128_kernel(
    const int* __restrict__ rowptr, const int* __restrict__ deg,
    const int* __restrict__ csr, const float* __restrict__ hs,
    const float* __restrict__ dis, float* __restrict__ out, int n) {
    int node = (blockIdx.x * 256 + threadIdx.x) >> 5;
    int lane = threadIdx.x & 31;
    if (node >= n) return;
    const float4* hs4 = (const float4*)hs;
    int start = rowptr[node], d = deg[node];
    int dm = min(d, 32);
    int uidx = (lane < dm) ? csr[start + lane] : 0;
    float dn = dis[node];
    float4 acc = hs4[(size_t)node * 32 + lane];
    acc.x *= dn; acc.y *= dn; acc.z *= dn; acc.w *= dn;
    for (int e = 0; e < dm; e++) {
        int u = __shfl_sync(FULLMASK, uidx, e);
        float du = dis[u];
        float4 v = hs4[(size_t)u * 32 + lane];
        acc.x += v.x * du; acc.y += v.y * du;
        acc.z += v.z * du; acc.w += v.w * du;
    }
    for (int e = 32; e < d; e++) {
        int u = csr[start + e];
        float du = dis[u];
        float4 v = hs4[(size_t)u * 32 + lane];
        acc.x += v.x * du; acc.y += v.y * du;
        acc.z += v.z * du; acc.w += v.w * du;
    }
    acc.x *= dn; acc.y *= dn; acc.z *= dn; acc.w *= dn;
    ((float4*)out)[(size_t)node * 32 + lane] = acc;
}

// ---------------- function-level mean pool (bf16 input) -----------------------
__global__ __launch_bounds__(256) void poolsegbf_kernel(
    const __nv_bfloat16* __restrict__ x, const int* __restrict__ start,
    float* __restrict__ pool, int nseg) {
    int f = (blockIdx.x * 256 + threadIdx.x) >> 5;
    int lane = threadIdx.x & 31;
    if (f >= nseg) return;
    int s = start[f], e = start[f + 1];
    const uint2* x8 = (const uint2*)x;
    float a0 = 0.f, a1 = 0.f, a2 = 0.f, a3 = 0.f;
    for (int i = s; i < e; i++) {
        uint2 raw = x8[(size_t)i * 32 + lane];
        float2 f0 = unpack_bf2(raw.x), f1 = unpack_bf2(raw.y);
        a0 += f0.x; a1 += f0.y; a2 += f1.x; a3 += f1.y;
    }
    float inv = 1.0f / (float)max(e - s, 1);
    ((float4*)pool)[(size_t)f * 32 + lane] = make_float4(a0 * inv, a1 * inv, a2 * inv, a3 * inv);
}

__global__ void assemble_kernel(const float* __restrict__ pool, const float* __restrict__ emb,
                                const int* __restrict__ src, const int* __restrict__ isext,
                                float* __restrict__ fx) {
    int i = blockIdx.x * blockDim.x + threadIdx.x;
    if (i >= N_FCG * D_H) return;
    int row = i >> 7, j = i & 127;
    int s = src[row];
    float v;
    if (isext[row] == 1) {
        int k = min(max(s, 0), VOCAB - 1);
        v = emb[(size_t)k * D_H + j];
    } else {
        int k = min(max(s, 0), N_FUNC - 1);
        v = pool[(size_t)k * D_H + j];
    }
    fx[i] = v;
}

__global__ __launch_bounds__(128) void gpool_kernel(
    const float* __restrict__ y, const int* __restrict__ start, float* __restrict__ g) {
    int b = blockIdx.x, col = threadIdx.x;
    int s = start[b], e = start[b + 1];
    float acc = 0.f;
    for (int i = s; i < e; i++) acc += y[(size_t)i * 128 + col];
    g[b * 128 + col] = acc / (float)max(e - s, 1);
}

__global__ __launch_bounds__(256) void head_kernel(
    const float* __restrict__ g,
    const float* __restrict__ Wp1, const float* __restrict__ bp1,
    const float* __restrict__ Wp2, const float* __restrict__ bp2,
    const float* __restrict__ Wp3, const float* __restrict__ bp3,
    float* __restrict__ out) {
    __shared__ float G[NB * 128], H1[NB * 64], H2[NB * 32];
    int t = threadIdx.x;
    for (int i = t; i < NB * 128; i += 256) G[i] = g[i];
    __syncthreads();
    for (int i = t; i < NB * 64; i += 256) {
        int r = i >> 6, c = i & 63;
        float a = bp1[c];
        for (int k = 0; k < 128; k++) a += G[r * 128 + k] * Wp1[k * 64 + c];
        H1[i] = fmaxf(a, 0.f);
    }
    __syncthreads();
    for (int i = t; i < NB * 32; i += 256) {
        int r = i >> 5, c = i & 31;
        float a = bp2[c];
        for (int k = 0; k < 64; k++) a += H1[r * 64 + k] * Wp2[k * 32 + c];
        H2[i] = fmaxf(a, 0.f);
    }
    __syncthreads();
    if (t < NB) {
        float a = bp3[0];
        for (int k = 0; k < 32; k++) a += H2[t * 32 + k] * Wp3[k];
        out[t] = 1.0f / (1.0f + expf(-a));
    }
}

// ---------------- launch ----------------------------------------------------
extern "C" void kernel_launch(void* const* d_in, const int* in_sizes, int n_in,
                              void* d_out, int out_size) {
    const float* cfg_x  = (const float*)d_in[0];
    const int*   cfg_ei = (const int*)  d_in[1];
    const int*   n2f    = (const int*)  d_in[2];
    const int*   fcg_ei = (const int*)  d_in[3];
    const int*   fbatch = (const int*)  d_in[4];
    const int*   fsrc   = (const int*)  d_in[5];
    const int*   fext   = (const int*)  d_in[6];
    const float* W1  = (const float*)d_in[7];
    const float* b1  = (const float*)d_in[8];
    const float* W2  = (const float*)d_in[9];
    const float* b2  = (const float*)d_in[10];
    const float* emb = (const float*)d_in[11];
    const float* Wf  = (const float*)d_in[12];
    const float* bf  = (const float*)d_in[13];
    const float* Wp1 = (const float*)d_in[14];
    const float* bp1 = (const float*)d_in[15];
    const float* Wp2 = (const float*)d_in[16];
    const float* bp2 = (const float*)d_in[17];
    const float* Wp3 = (const float*)d_in[18];
    const float* bp3 = (const float*)d_in[19];
    float* out = (float*)d_out;

    void *p;
    cudaGetSymbolAddress(&p, g_b);       __nv_bfloat16* HB2 = (__nv_bfloat16*)p;
    cudaGetSymbolAddress(&p, g_hb);      __nv_bfloat16* HB = (__nv_bfloat16*)p;
    cudaGetSymbolAddress(&p, g_wb1);     __nv_bfloat16* Wb1 = (__nv_bfloat16*)p;
    cudaGetSymbolAddress(&p, g_wb2);     __nv_bfloat16* Wb2 = (__nv_bfloat16*)p;
    cudaGetSymbolAddress(&p, g_deg);     int*   deg    = (int*)p;
    cudaGetSymbolAddress(&p, g_dis);     float* dis    = (float*)p;
    cudaGetSymbolAddress(&p, g_rowptr);  int*   rowptr = (int*)p;
    cudaGetSymbolAddress(&p, g_csr);     int*   csr    = (int*)p;
    cudaGetSymbolAddress(&p, g_fdeg);    int*   fdeg   = (int*)p;
    cudaGetSymbolAddress(&p, g_fdis);    float* fdis   = (float*)p;
    cudaGetSymbolAddress(&p, g_frowptr); int*   frowptr= (int*)p;
    cudaGetSymbolAddress(&p, g_fcsr);    int*   fcsr   = (int*)p;
    cudaGetSymbolAddress(&p, g_fstart);  int*   fstart = (int*)p;
    cudaGetSymbolAddress(&p, g_bstart);  int*   bstart = (int*)p;
    cudaGetSymbolAddress(&p, g_pool);    float* pool   = (float*)p;
    cudaGetSymbolAddress(&p, g_fx);      float* fx     = (float*)p;
    cudaGetSymbolAddress(&p, g_fz);      float* fz     = (float*)p;
    cudaGetSymbolAddress(&p, g_fy);      float* fy     = (float*)p;
    cudaGetSymbolAddress(&p, g_g);       float* gg     = (float*)p;

    // dynamic smem sizes for the fused kernels
    const int SM1 = 128 * (64 + 8) * 2 + 32 * 136 * 2 + 8 * 320 * 4 + 128 * 4;   // ~38 KB
    const int SM2 = 128 * (128 + 8) * 2 + 32 * 136 * 2 + 8 * 320 * 4 + 128 * 4;  // ~55 KB
    static bool attr_set = false;
    cudaFuncSetAttribute(gemmfused_kernel<64, true, true>,
                         cudaFuncAttributeMaxDynamicSharedMemorySize, SM1);
    cudaFuncSetAttribute(gemmfused_kernel<128, false, false>,
                         cudaFuncAttributeMaxDynamicSharedMemorySize, SM2);
    (void)attr_set;

    // prolog: init + degrees
    init_kernel<<<(N_CFG + 255) / 256, 256>>>(W1, W2);
    deg_all_kernel<<<(E_CFG + E_FCG + 255) / 256, 256>>>(cfg_ei, fcg_ei);

    // CSR build (merged)
    scan_local_all<<<NBLK_CFG + NBLK_FCG, 256>>>();
    scan_bsum_all<<<2, 512>>>();
    scan_add_all<<<(N_CFG + N_FCG + N_FUNC + NB + 2 + 255) / 256, 256>>>(n2f, fbatch);
    fill_csr_all<<<(E_CFG + E_FCG + 255) / 256, 256>>>(cfg_ei, fcg_ei);

    // CFG layer 1: fused gather(fp32 cfg_x) + GEMM -> HB (bf16)
    gemmfused_kernel<64, true, true><<<N_CFG / 128, 256, SM1>>>(
        cfg_x, rowptr, deg, csr, Wb1, b1, dis, HB, N_CFG);

    // CFG layer 2: fused gather(HB bf16) + GEMM -> HB2 (separate buffer, no race)
    gemmfused_kernel<128, false, false><<<N_CFG / 128, 256, SM2>>>(
        HB, rowptr, deg, csr, Wb2, b2, dis, HB2, N_CFG);

    // function-level mean pool (bf16 input)
    poolsegbf_kernel<<<(N_FUNC * 32 + 255) / 256, 256>>>(HB2, fstart, pool, N_FUNC);

    // FCG features + FCG layer (fp32)
    assemble_kernel<<<(N_FCG * D_H) / 256, 256>>>(pool, emb, fsrc, fext, fx);
    gather128_kernel<<<(N_FCG * 32 + 255) / 256, 256>>>(frowptr, fdeg, fcsr, fx, fdis, fz, N_FCG);
    gemmx_kernel<128, false><<<(N_FCG + 127) / 128, 256>>>(fz, Wf, bf, fdis, fy, N_FCG);

    // binary-level mean pool + head
    gpool_kernel<<<NB, 128>>>(fy, bstart, gg);
    head_kernel<<<1, 256>>>(gg, Wp1, bp1, Wp2, bp2, Wp3, bp3, out);
}

// round 15
// speedup vs baseline: 1.1597x; 1.1597x over previous
#include <cuda_runtime.h>
#include <cuda_bf16.h>
#include <mma.h>
#include <math.h>

using namespace nvcuda;

#define N_CFG 400000
#define E_CFG 1600000
#define N_FUNC 8000
#define N_FCG 9600
#define E_FCG 80000
#define NB 8
#define D_H 128
#define VOCAB 10002
#define FULLMASK 0xffffffffu

// ---------------- scratch (device globals) ----------------------------------
__device__ float g_b [(size_t)N_CFG * D_H];
__device__ __nv_bfloat16 g_hb[(size_t)N_CFG * D_H];
__device__ __nv_bfloat16 g_wb1[64 * 128];
__device__ __nv_bfloat16 g_wb2[128 * 128];
__device__ int   g_deg[N_CFG];
__device__ float g_dis[N_CFG];
__device__ int   g_rowptr[N_CFG];
__device__ int   g_cursor[N_CFG];
__device__ int   g_csr[E_CFG];
__device__ int   g_fdeg[N_FCG];
__device__ float g_fdis[N_FCG];
__device__ int   g_frowptr[N_FCG];
__device__ int   g_fcursor[N_FCG];
__device__ int   g_fcsr[E_FCG];
__device__ int   g_bsum[512];          // [0..399]=CFG blocks, [400..]=FCG blocks
__device__ int   g_fstart[N_FUNC + 1];
__device__ int   g_bstart[NB + 1];
__device__ float g_pool[N_FUNC * D_H];
__device__ float g_fz [N_FCG * D_H];
__device__ float g_fy [N_FCG * D_H];
__device__ float g_g  [NB * D_H];

#define NBLK_CFG ((N_CFG + 1023) / 1024)   // 391
#define NBLK_FCG ((N_FCG + 1023) / 1024)   // 10
#define FBSUM 400

static __device__ __forceinline__ unsigned pack_bf2(float a, float b) {
    __nv_bfloat162 h = __float22bfloat162_rn(make_float2(a, b));
    return *reinterpret_cast<unsigned*>(&h);
}
static __device__ __forceinline__ float2 unpack_bf2(unsigned u) {
    return __bfloat1622float2(*reinterpret_cast<const __nv_bfloat162*>(&u));
}

// ---------------- init: zero degs + weight->bf16 ------------------------------
__global__ void init_kernel(const float* __restrict__ W1, const float* __restrict__ W2) {
    int i = blockIdx.x * blockDim.x + threadIdx.x;
    if (i < N_CFG) g_deg[i] = 0;
    if (i < N_FCG) g_fdeg[i] = 0;
    if (i < 64 * 128) g_wb1[i] = __float2bfloat16(W1[i]);
    if (i >= 64 * 128 && i < 64 * 128 + 128 * 128)
        g_wb2[i - 64 * 128] = __float2bfloat16(W2[i - 64 * 128]);
}
__global__ void deg_all_kernel(const int* __restrict__ cei, const int* __restrict__ fei) {
    int i = blockIdx.x * blockDim.x + threadIdx.x;
    if (i < E_CFG) {
        atomicAdd(&g_deg[cei[E_CFG + i]], 1);
    } else if (i < E_CFG + E_FCG) {
        atomicAdd(&g_fdeg[fei[E_FCG + (i - E_CFG)]], 1);
    }
}

// ---------------- CSR build (CFG+FCG merged per stage; dis fused in) ---------
__device__ __forceinline__ void scan_local_body(const int* cnt, int n, int* out,
                                                int* bsum, float* dis, int blk, int t) {
    __shared__ int s[256];
    int base = blk * 1024;
    int v[4], sum = 0;
#pragma unroll
    for (int j = 0; j < 4; j++) {
        int i = base + t * 4 + j;
        v[j] = (i < n) ? cnt[i] : 0;
        if (i < n) dis[i] = rsqrtf((float)v[j] + 1.0f);   // fused norm
        sum += v[j];
    }
    s[t] = sum;
    __syncthreads();
    for (int off = 1; off < 256; off <<= 1) {
        int x = (t >= off) ? s[t - off] : 0;
        __syncthreads();
        s[t] += x;
        __syncthreads();
    }
    if (t == 255) bsum[blk] = s[255];
    int run = (t > 0) ? s[t - 1] : 0;
#pragma unroll
    for (int j = 0; j < 4; j++) {
        int i = base + t * 4 + j;
        if (i < n) out[i] = run;
        run += v[j];
    }
}
__global__ void scan_local_all() {
    if (blockIdx.x < NBLK_CFG)
        scan_local_body(g_deg, N_CFG, g_rowptr, g_bsum, g_dis, blockIdx.x, threadIdx.x);
    else
        scan_local_body(g_fdeg, N_FCG, g_frowptr, g_bsum + FBSUM, g_fdis,
                        blockIdx.x - NBLK_CFG, threadIdx.x);
}
__global__ void scan_bsum_all() {
    __shared__ int s[512];
    int* bsum = (blockIdx.x == 0) ? g_bsum : g_bsum + FBSUM;
    int nb = (blockIdx.x == 0) ? NBLK_CFG : NBLK_FCG;
    int t = threadIdx.x;
    s[t] = (t < nb) ? bsum[t] : 0;
    __syncthreads();
    for (int off = 1; off < 512; off <<= 1) {
        int x = (t >= off) ? s[t - off] : 0;
        __syncthreads();
        s[t] += x;
        __syncthreads();
    }
    if (t < nb) bsum[t] = (t > 0) ? s[t - 1] : 0;
}
// scan_add + segment bounds, one grid
__global__ void scan_add_all(const int* __restrict__ n2f, const int* __restrict__ fbatch) {
    int i = blockIdx.x * blockDim.x + threadIdx.x;
    if (i < N_CFG) {
        int v = g_rowptr[i] + g_bsum[i >> 10];
        g_rowptr[i] = v;
        g_cursor[i] = v;
    } else if (i < N_CFG + N_FCG) {
        int j = i - N_CFG;
        int v = g_frowptr[j] + g_bsum[FBSUM + (j >> 10)];
        g_frowptr[j] = v;
        g_fcursor[j] = v;
    } else if (i <= N_CFG + N_FCG + N_FUNC) {
        int f = i - (N_CFG + N_FCG);
        int lo = 0, hi = N_CFG;
        while (lo < hi) {
            int mid = (lo + hi) >> 1;
            if (n2f[mid] < f) lo = mid + 1; else hi = mid;
        }
        g_fstart[f] = lo;
    } else if (i <= N_CFG + N_FCG + N_FUNC + 1 + NB) {
        int f = i - (N_CFG + N_FCG + N_FUNC + 1);
        int lo = 0, hi = N_FCG;
        while (lo < hi) {
            int mid = (lo + hi) >> 1;
            if (fbatch[mid] < f) lo = mid + 1; else hi = mid;
        }
        g_bstart[f] = lo;
    }
}
__global__ void fill_csr_all(const int* __restrict__ cei, const int* __restrict__ fei) {
    int i = blockIdx.x * blockDim.x + threadIdx.x;
    if (i < E_CFG) {
        int r = cei[i], c = cei[E_CFG + i];
        int slot = atomicAdd(&g_cursor[c], 1);
        g_csr[slot] = r;
    } else if (i < E_CFG + E_FCG) {
        int j = i - E_CFG;
        int r = fei[j], c = fei[E_FCG + j];
        int slot = atomicAdd(&g_fcursor[c], 1);
        g_fcsr[slot] = r;
    }
}

// ---------------- WMMA bf16 GEMM ---------------------------------------------
template<int K, bool SCALE, bool OUTBF16>
__global__ __launch_bounds__(256, 2) void gemmw_kernel(
    const __nv_bfloat16* __restrict__ X, const __nv_bfloat16* __restrict__ Wb,
    const float* __restrict__ bias, const float* __restrict__ dis,
    float* __restrict__ H, __nv_bfloat16* __restrict__ HB, int N) {
    constexpr int AP = 40;
    constexpr int WP = 136;
    __shared__ __nv_bfloat16 As[128 * AP];
    __shared__ __nv_bfloat16 Ws[32 * WP];
    __shared__ float Eb[8][16 * 20];
    __shared__ float Bs[128];

    const int tid = threadIdx.x;
    const int warp = tid >> 5, lane = tid & 31;
    const int wr = warp >> 2;
    const int wc = warp & 3;
    const int row0 = blockIdx.x * 128;

    if (tid < 128) Bs[tid] = bias[tid];

    wmma::fragment<wmma::accumulator, 16, 16, 16, float> acc[4][2];
#pragma unroll
    for (int i = 0; i < 4; i++)
#pragma unroll
        for (int j = 0; j < 2; j++) wmma::fill_fragment(acc[i][j], 0.0f);

    const unsigned* Xu = (const unsigned*)X;
    const unsigned* Wu = (const unsigned*)Wb;
    unsigned* Asu = (unsigned*)As;
    unsigned* Wsu = (unsigned*)Ws;

    for (int kc = 0; kc < K; kc += 32) {
#pragma unroll
        for (int i = tid; i < 128 * 16; i += 256) {
            int r = i >> 4, k2 = i & 15;
            Asu[r * (AP / 2) + k2] = Xu[(size_t)(row0 + r) * (K / 2) + (kc >> 1) + k2];
        }
#pragma unroll
        for (int i = tid; i < 32 * 64; i += 256) {
            int k = i >> 6, c2 = i & 63;
            Wsu[k * (WP / 2) + c2] = Wu[(size_t)(kc + k) * 64 + c2];
        }
        __syncthreads();
#pragma unroll
        for (int ks = 0; ks < 32; ks += 16) {
            wmma::fragment<wmma::matrix_a, 16, 16, 16, __nv_bfloat16, wmma::row_major> af[4];
            wmma::fragment<wmma::matrix_b, 16, 16, 16, __nv_bfloat16, wmma::row_major> bf[2];
#pragma unroll
            for (int i = 0; i < 4; i++)
                wmma::load_matrix_sync(af[i], &As[(wr * 64 + i * 16) * AP + ks], AP);
#pragma unroll
            for (int j = 0; j < 2; j++)
                wmma::load_matrix_sync(bf[j], &Ws[ks * WP + wc * 32 + j * 16], WP);
#pragma unroll
            for (int i = 0; i < 4; i++)
#pragma unroll
                for (int j = 0; j < 2; j++)
                    wmma::mma_sync(acc[i][j], af[i], bf[j], acc[i][j]);
        }
        __syncthreads();
    }

    const int r = lane >> 1, c8 = (lane & 1) * 8;
#pragma unroll
    for (int i = 0; i < 4; i++) {
#pragma unroll
        for (int j = 0; j < 2; j++) {
            wmma::store_matrix_sync(&Eb[warp][0], acc[i][j], 20, wmma::mem_row_major);
            __syncwarp();
            int gr = row0 + wr * 64 + i * 16 + r;
            int gc = wc * 32 + j * 16 + c8;
            float s = SCALE ? dis[gr] : 1.0f;
            float o[8];
#pragma unroll
            for (int q = 0; q < 8; q++)
                o[q] = fmaxf(Eb[warp][r * 20 + c8 + q] + Bs[gc + q], 0.0f) * s;
            if (OUTBF16) {
                uint4 pk;
                pk.x = pack_bf2(o[0], o[1]); pk.y = pack_bf2(o[2], o[3]);
                pk.z = pack_bf2(o[4], o[5]); pk.w = pack_bf2(o[6], o[7]);
                *(uint4*)&HB[(size_t)gr * 128 + gc] = pk;
            } else {
                *(float4*)&H[(size_t)gr * 128 + gc]     = make_float4(o[0], o[1], o[2], o[3]);
                *(float4*)&H[(size_t)gr * 128 + gc + 4] = make_float4(o[4], o[5], o[6], o[7]);
            }
            __syncwarp();
        }
    }
}

// ---------------- FFMA2 GEMM (fp32, FCG) --------------------------------------
template<int K, bool SCALE>
__global__ __launch_bounds__(256, 2) void gemmx_kernel(
    const float* __restrict__ X, const float* __restrict__ W,
    const float* __restrict__ bias, const float* __restrict__ dis,
    float* __restrict__ H, int N) {
    __shared__ float Xs[32 * 132];
    __shared__ float Ws[32 * 128];
    const int row0 = blockIdx.x * 128;
    const int tx = threadIdx.x & 15;
    const int ty = threadIdx.x >> 4;
    const int c0 = tx * 8, r0 = ty * 8;

    unsigned long long acc2[8][4];
#pragma unroll
    for (int r = 0; r < 8; r++)
#pragma unroll
        for (int j = 0; j < 4; j++) acc2[r][j] = 0ULL;

    for (int kc = 0; kc < K; kc += 32) {
#pragma unroll
        for (int i = threadIdx.x; i < 128 * 32; i += 256) {
            int k = i & 31, r = i >> 5;
            int gr = row0 + r;
            Xs[k * 132 + r] = (gr < N) ? X[(size_t)gr * K + kc + k] : 0.f;
        }
#pragma unroll
        for (int i = threadIdx.x; i < 32 * 128; i += 256) {
            int c = i & 127, k = i >> 7;
            Ws[k * 128 + c] = W[(size_t)(kc + k) * 128 + c];
        }
        __syncthreads();
#pragma unroll 4
        for (int k = 0; k < 32; k++) {
            float4 al = *(const float4*)&Xs[k * 132 + r0];
            float4 ah = *(const float4*)&Xs[k * 132 + r0 + 4];
            ulonglong2 wl = *(const ulonglong2*)&Ws[k * 128 + c0];
            ulonglong2 wh = *(const ulonglong2*)&Ws[k * 128 + c0 + 4];
            unsigned long long w2[4];
            w2[0] = wl.x; w2[1] = wl.y; w2[2] = wh.x; w2[3] = wh.y;
            float a[8];
            a[0] = al.x; a[1] = al.y; a[2] = al.z; a[3] = al.w;
            a[4] = ah.x; a[5] = ah.y; a[6] = ah.z; a[7] = ah.w;
#pragma unroll
            for (int r = 0; r < 8; r++) {
                unsigned long long a2;
                asm("mov.b64 %0, {%1, %1};" : "=l"(a2) : "f"(a[r]));
#pragma unroll
                for (int j = 0; j < 4; j++)
                    asm("fma.rn.f32x2 %0, %1, %2, %0;"
                        : "+l"(acc2[r][j]) : "l"(a2), "l"(w2[j]));
            }
        }
        __syncthreads();
    }

    float bb[8];
#pragma unroll
    for (int j = 0; j < 8; j++) bb[j] = bias[c0 + j];
#pragma unroll
    for (int r = 0; r < 8; r++) {
        int gr = row0 + r0 + r;
        if (gr >= N) return;
        float s = SCALE ? dis[gr] : 1.0f;
        float o[8];
#pragma unroll
        for (int j = 0; j < 4; j++) {
            float lo, hi;
            asm("mov.b64 {%0, %1}, %2;" : "=f"(lo), "=f"(hi) : "l"(acc2[r][j]));
            o[2 * j]     = fmaxf(lo + bb[2 * j], 0.f) * s;
            o[2 * j + 1] = fmaxf(hi + bb[2 * j + 1], 0.f) * s;
        }
        *(float4*)&H[(size_t)gr * 128 + c0]     = make_float4(o[0], o[1], o[2], o[3]);
        *(float4*)&H[(size_t)gr * 128 + c0 + 4] = make_float4(o[4], o[5], o[6], o[7]);
    }
}

// ---------------- gather 64ch direct from fp32 cfg_x (tobf fused) -------------
// quarter-warp per node: 8 lanes x 2 float4 (32B) = 256B fp32 row.
__global__ __launch_bounds__(256) void gather64f_kernel(
    const int* __restrict__ rowptr, const int* __restrict__ deg,
    const int* __restrict__ csr, const float4* __restrict__ x,
    const float* __restrict__ dis, uint4* __restrict__ out, int n) {
    int lane = threadIdx.x & 31;
    int q = lane >> 3;
    int sub = lane & 7;
    int node = ((blockIdx.x * 256 + threadIdx.x) >> 5) * 4 + q;
    if (node >= n) return;
    int start = rowptr[node], d = deg[node];
    int dm = min(d, 8);
    int uidx = (sub < dm) ? csr[start + sub] : 0;
    int u[8];
#pragma unroll
    for (int j = 0; j < 8; j++) u[j] = __shfl_sync(FULLMASK, uidx, (q << 3) + j);
    float dn = dis[node];
    float a[8];
    {
        float4 s0 = x[(size_t)node * 16 + sub * 2];
        float4 s1 = x[(size_t)node * 16 + sub * 2 + 1];
        a[0] = s0.x * dn; a[1] = s0.y * dn; a[2] = s0.z * dn; a[3] = s0.w * dn;
        a[4] = s1.x * dn; a[5] = s1.y * dn; a[6] = s1.z * dn; a[7] = s1.w * dn;
    }
#pragma unroll
    for (int j = 0; j < 8; j++) {
        if (j < dm) {
            float du = dis[u[j]];
            float4 r0 = x[(size_t)u[j] * 16 + sub * 2];
            float4 r1 = x[(size_t)u[j] * 16 + sub * 2 + 1];
            a[0] += r0.x * du; a[1] += r0.y * du; a[2] += r0.z * du; a[3] += r0.w * du;
            a[4] += r1.x * du; a[5] += r1.y * du; a[6] += r1.z * du; a[7] += r1.w * du;
        }
    }
    for (int e = 8; e < d; e++) {       // ~2% of nodes
        int uu = csr[start + e];
        float du = dis[uu];
        float4 r0 = x[(size_t)uu * 16 + sub * 2];
        float4 r1 = x[(size_t)uu * 16 + sub * 2 + 1];
        a[0] += r0.x * du; a[1] += r0.y * du; a[2] += r0.z * du; a[3] += r0.w * du;
        a[4] += r1.x * du; a[5] += r1.y * du; a[6] += r1.z * du; a[7] += r1.w * du;
    }
    uint4 pk;
    pk.x = pack_bf2(a[0] * dn, a[1] * dn);
    pk.y = pack_bf2(a[2] * dn, a[3] * dn);
    pk.z = pack_bf2(a[4] * dn, a[5] * dn);
    pk.w = pack_bf2(a[6] * dn, a[7] * dn);
    out[(size_t)node * 8 + sub] = pk;
}

// ---------------- gather 128ch bf16, quarter-warp, fully unrolled -------------
__global__ __launch_bounds__(256) void gather128bf_kernel(
    const int* __restrict__ rowptr, const int* __restrict__ deg,
    const int* __restrict__ csr, const __nv_bfloat16* __restrict__ hb,
    const float* __restrict__ dis, uint4* __restrict__ out, int n) {
    int lane = threadIdx.x & 31;
    int q = lane >> 3;
    int sub = lane & 7;
    int node = ((blockIdx.x * 256 + threadIdx.x) >> 5) * 4 + q;
    if (node >= n) return;
    const uint4* h16 = (const uint4*)hb;
    int start = rowptr[node], d = deg[node];
    int dm = min(d, 8);
    int uidx = (sub < dm) ? csr[start + sub] : 0;
    int u[8];
#pragma unroll
    for (int j = 0; j < 8; j++) u[j] = __shfl_sync(FULLMASK, uidx, (q << 3) + j);
    float acc[16];
    {
        uint4 r0 = h16[(size_t)node * 16 + sub];
        uint4 r1 = h16[(size_t)node * 16 + 8 + sub];
        float2 f0 = unpack_bf2(r0.x), f1 = unpack_bf2(r0.y);
        float2 f2 = unpack_bf2(r0.z), f3 = unpack_bf2(r0.w);
        float2 g0 = unpack_bf2(r1.x), g1 = unpack_bf2(r1.y);
        float2 g2 = unpack_bf2(r1.z), g3 = unpack_bf2(r1.w);
        acc[0] = f0.x;  acc[1] = f0.y;  acc[2] = f1.x;  acc[3] = f1.y;
        acc[4] = f2.x;  acc[5] = f2.y;  acc[6] = f3.x;  acc[7] = f3.y;
        acc[8] = g0.x;  acc[9] = g0.y;  acc[10] = g1.x; acc[11] = g1.y;
        acc[12] = g2.x; acc[13] = g2.y; acc[14] = g3.x; acc[15] = g3.y;
    }
#pragma unroll
    for (int j = 0; j < 8; j++) {
        if (j < dm) {
            uint4 r0 = h16[(size_t)u[j] * 16 + sub];
            uint4 r1 = h16[(size_t)u[j] * 16 + 8 + sub];
            float2 f0 = unpack_bf2(r0.x), f1 = unpack_bf2(r0.y);
            float2 f2 = unpack_bf2(r0.z), f3 = unpack_bf2(r0.w);
            float2 g0 = unpack_bf2(r1.x), g1 = unpack_bf2(r1.y);
            float2 g2 = unpack_bf2(r1.z), g3 = unpack_bf2(r1.w);
            acc[0] += f0.x;  acc[1] += f0.y;  acc[2] += f1.x;  acc[3] += f1.y;
            acc[4] += f2.x;  acc[5] += f2.y;  acc[6] += f3.x;  acc[7] += f3.y;
            acc[8] += g0.x;  acc[9] += g0.y;  acc[10] += g1.x; acc[11] += g1.y;
            acc[12] += g2.x; acc[13] += g2.y; acc[14] += g3.x; acc[15] += g3.y;
        }
    }
    for (int e = 8; e < d; e++) {
        int uu = csr[start + e];
        uint4 r0 = h16[(size_t)uu * 16 + sub];
        uint4 r1 = h16[(size_t)uu * 16 + 8 + sub];
        float2 f0 = unpack_bf2(r0.x), f1 = unpack_bf2(r0.y);
        float2 f2 = unpack_bf2(r0.z), f3 = unpack_bf2(r0.w);
        float2 g0 = unpack_bf2(r1.x), g1 = unpack_bf2(r1.y);
        float2 g2 = unpack_bf2(r1.z), g3 = unpack_bf2(r1.w);
        acc[0] += f0.x;  acc[1] += f0.y;  acc[2] += f1.x;  acc[3] += f1.y;
        acc[4] += f2.x;  acc[5] += f2.y;  acc[6] += f3.x;  acc[7] += f3.y;
        acc[8] += g0.x;  acc[9] += g0.y;  acc[10] += g1.x; acc[11] += g1.y;
        acc[12] += g2.x; acc[13] += g2.y; acc[14] += g3.x; acc[15] += g3.y;
    }
    float dn = dis[node];
    uint4 pk0, pk1;
    pk0.x = pack_bf2(acc[0] * dn, acc[1] * dn);
    pk0.y = pack_bf2(acc[2] * dn, acc[3] * dn);
    pk0.z = pack_bf2(acc[4] * dn, acc[5] * dn);
    pk0.w = pack_bf2(acc[6] * dn, acc[7] * dn);
    pk1.x = pack_bf2(acc[8] * dn, acc[9] * dn);
    pk1.y = pack_bf2(acc[10] * dn, acc[11] * dn);
    pk1.z = pack_bf2(acc[12] * dn, acc[13] * dn);
    pk1.w = pack_bf2(acc[14] * dn, acc[15] * dn);
    out[(size_t)node * 16 + sub] = pk0;
    out[(size_t)node * 16 + 8 + sub] = pk1;
}

// ---------------- FCG gather with assemble fused ------------------------------
// row(i) = isext[i] ? emb[clip(src)] : pool[clip(src)]; aggregate with dis.
static __device__ __forceinline__ float4 fcg_row(
    const float4* __restrict__ pool4, const float4* __restrict__ emb4,
    const int* __restrict__ src, const int* __restrict__ isext, int i, int lane) {
    int s = src[i];
    if (isext[i] == 1) {
        int k = min(max(s, 0), VOCAB - 1);
        return emb4[(size_t)k * 32 + lane];
    } else {
        int k = min(max(s, 0), N_FUNC - 1);
        return pool4[(size_t)k * 32 + lane];
    }
}
__global__ __launch_bounds__(256) void gather128a_kernel(
    const int* __restrict__ rowptr, const int* __restrict__ deg,
    const int* __restrict__ csr,
    const float* __restrict__ pool, const float* __restrict__ emb,
    const int* __restrict__ src, const int* __restrict__ isext,
    const float* __restrict__ dis, float* __restrict__ out, int n) {
    int node = (blockIdx.x * 256 + threadIdx.x) >> 5;
    int lane = threadIdx.x & 31;
    if (node >= n) return;
    const float4* pool4 = (const float4*)pool;
    const float4* emb4 = (const float4*)emb;
    int start = rowptr[node], d = deg[node];
    int dm = min(d, 32);
    int uidx = (lane < dm) ? csr[start + lane] : 0;
    float dn = dis[node];
    float4 acc = fcg_row(pool4, emb4, src, isext, node, lane);
    acc.x *= dn; acc.y *= dn; acc.z *= dn; acc.w *= dn;
    for (int e = 0; e < dm; e++) {
        int u = __shfl_sync(FULLMASK, uidx, e);
        float du = dis[u];
        float4 v = fcg_row(pool4, emb4, src, isext, u, lane);
        acc.x += v.x * du; acc.y += v.y * du;
        acc.z += v.z * du; acc.w += v.w * du;
    }
    for (int e = 32; e < d; e++) {
        int u = csr[start + e];
        float du = dis[u];
        float4 v = fcg_row(pool4, emb4, src, isext, u, lane);
        acc.x += v.x * du; acc.y += v.y * du;
        acc.z += v.z * du; acc.w += v.w * du;
    }
    acc.x *= dn; acc.y *= dn; acc.z *= dn; acc.w *= dn;
    ((float4*)out)[(size_t)node * 32 + lane] = acc;
}

// ---------------- function-level mean pool (bf16 input) -----------------------
__global__ __launch_bounds__(256) void poolsegbf_kernel(
    const __nv_bfloat16* __restrict__ x, const int* __restrict__ start,
    float* __restrict__ pool, int nseg) {
    int f = (blockIdx.x * 256 + threadIdx.x) >> 5;
    int lane = threadIdx.x & 31;
    if (f >= nseg) return;
    int s = start[f], e = start[f + 1];
    const uint2* x8 = (const uint2*)x;
    float a0 = 0.f, a1 = 0.f, a2 = 0.f, a3 = 0.f;
    for (int i = s; i < e; i++) {
        uint2 raw = x8[(size_t)i * 32 + lane];
        float2 f0 = unpack_bf2(raw.x), f1 = unpack_bf2(raw.y);
        a0 += f0.x; a1 += f0.y; a2 += f1.x; a3 += f1.y;
    }
    float inv = 1.0f / (float)max(e - s, 1);
    ((float4*)pool)[(size_t)f * 32 + lane] = make_float4(a0 * inv, a1 * inv, a2 * inv, a3 * inv);
}

__global__ __launch_bounds__(128) void gpool_kernel(
    const float* __restrict__ y, const int* __restrict__ start, float* __restrict__ g) {
    int b = blockIdx.x, col = threadIdx.x;
    int s = start[b], e = start[b + 1];
    float acc = 0.f;
    for (int i = s; i < e; i++) acc += y[(size_t)i * 128 + col];
    g[b * 128 + col] = acc / (float)max(e - s, 1);
}

__global__ __launch_bounds__(256) void head_kernel(
    const float* __restrict__ g,
    const float* __restrict__ Wp1, const float* __restrict__ bp1,
    const float* __restrict__ Wp2, const float* __restrict__ bp2,
    const float* __restrict__ Wp3, const float* __restrict__ bp3,
    float* __restrict__ out) {
    __shared__ float G[NB * 128], H1[NB * 64], H2[NB * 32];
    int t = threadIdx.x;
    for (int i = t; i < NB * 128; i += 256) G[i] = g[i];
    __syncthreads();
    for (int i = t; i < NB * 64; i += 256) {
        int r = i >> 6, c = i & 63;
        float a = bp1[c];
        for (int k = 0; k < 128; k++) a += G[r * 128 + k] * Wp1[k * 64 + c];
        H1[i] = fmaxf(a, 0.f);
    }
    __syncthreads();
    for (int i = t; i < NB * 32; i += 256) {
        int r = i >> 5, c = i & 31;
        float a = bp2[c];
        for (int k = 0; k < 64; k++) a += H1[r * 64 + k] * Wp2[k * 32 + c];
        H2[i] = fmaxf(a, 0.f);
    }
    __syncthreads();
    if (t < NB) {
        float a = bp3[0];
        for (int k = 0; k < 32; k++) a += H2[t * 32 + k] * Wp3[k];
        out[t] = 1.0f / (1.0f + expf(-a));
    }
}

// ---------------- launch ----------------------------------------------------
extern "C" void kernel_launch(void* const* d_in, const int* in_sizes, int n_in,
                              void* d_out, int out_size) {
    const float* cfg_x  = (const float*)d_in[0];
    const int*   cfg_ei = (const int*)  d_in[1];
    const int*   n2f    = (const int*)  d_in[2];
    const int*   fcg_ei = (const int*)  d_in[3];
    const int*   fbatch = (const int*)  d_in[4];
    const int*   fsrc   = (const int*)  d_in[5];
    const int*   fext   = (const int*)  d_in[6];
    const float* W1  = (const float*)d_in[7];
    const float* b1  = (const float*)d_in[8];
    const float* W2  = (const float*)d_in[9];
    const float* b2  = (const float*)d_in[10];
    const float* emb = (const float*)d_in[11];
    const float* Wf  = (const float*)d_in[12];
    const float* bf  = (const float*)d_in[13];
    const float* Wp1 = (const float*)d_in[14];
    const float* bp1 = (const float*)d_in[15];
    const float* Wp2 = (const float*)d_in[16];
    const float* bp2 = (const float*)d_in[17];
    const float* Wp3 = (const float*)d_in[18];
    const float* bp3 = (const float*)d_in[19];
    float* out = (float*)d_out;

    void *p;
    cudaGetSymbolAddress(&p, g_b);       float* Bb     = (float*)p;
    cudaGetSymbolAddress(&p, g_hb);      __nv_bfloat16* HB = (__nv_bfloat16*)p;
    cudaGetSymbolAddress(&p, g_wb1);     __nv_bfloat16* Wb1 = (__nv_bfloat16*)p;
    cudaGetSymbolAddress(&p, g_wb2);     __nv_bfloat16* Wb2 = (__nv_bfloat16*)p;
    cudaGetSymbolAddress(&p, g_deg);     int*   deg    = (int*)p;
    cudaGetSymbolAddress(&p, g_dis);     float* dis    = (float*)p;
    cudaGetSymbolAddress(&p, g_rowptr);  int*   rowptr = (int*)p;
    cudaGetSymbolAddress(&p, g_csr);     int*   csr    = (int*)p;
    cudaGetSymbolAddress(&p, g_fdeg);    int*   fdeg   = (int*)p;
    cudaGetSymbolAddress(&p, g_fdis);    float* fdis   = (float*)p;
    cudaGetSymbolAddress(&p, g_frowptr); int*   frowptr= (int*)p;
    cudaGetSymbolAddress(&p, g_fcsr);    int*   fcsr   = (int*)p;
    cudaGetSymbolAddress(&p, g_fstart);  int*   fstart = (int*)p;
    cudaGetSymbolAddress(&p, g_bstart);  int*   bstart = (int*)p;
    cudaGetSymbolAddress(&p, g_pool);    float* pool   = (float*)p;
    cudaGetSymbolAddress(&p, g_fz);      float* fz     = (float*)p;
    cudaGetSymbolAddress(&p, g_fy);      float* fy     = (float*)p;
    cudaGetSymbolAddress(&p, g_g);       float* gg     = (float*)p;

    unsigned* z1b = (unsigned*)Bb;                   // gather1 out, 64ch bf16
    uint4*    z2b = (uint4*)Bb + (size_t)N_CFG * 8;  // gather2 out, 128ch bf16

    // prolog: init + degrees (dis fused into scan)
    init_kernel<<<(N_CFG + 255) / 256, 256>>>(W1, W2);
    deg_all_kernel<<<(E_CFG + E_FCG + 255) / 256, 256>>>(cfg_ei, fcg_ei);

    // CSR build (merged; dis in scan_local; bounds in scan_add)
    scan_local_all<<<NBLK_CFG + NBLK_FCG, 256>>>();
    scan_bsum_all<<<2, 512>>>();
    scan_add_all<<<(N_CFG + N_FCG + N_FUNC + NB + 2 + 255) / 256, 256>>>(n2f, fbatch);
    fill_csr_all<<<(E_CFG + E_FCG + 255) / 256, 256>>>(cfg_ei, fcg_ei);

    // CFG layer 1 (direct fp32 gather, tobf fused)
    gather64f_kernel<<<(N_CFG + 31) / 32, 256>>>(rowptr, deg, csr,
                                                 (const float4*)cfg_x, dis, (uint4*)z1b, N_CFG);
    gemmw_kernel<64, true, true><<<N_CFG / 128, 256>>>(
        (const __nv_bfloat16*)z1b, Wb1, b1, dis, nullptr, HB, N_CFG);

    // CFG layer 2
    gather128bf_kernel<<<(N_CFG + 31) / 32, 256>>>(rowptr, deg, csr, HB, dis, z2b, N_CFG);
    gemmw_kernel<128, false, true><<<N_CFG / 128, 256>>>(
        (const __nv_bfloat16*)z2b, Wb2, b2, dis, nullptr, HB, N_CFG);

    // function-level mean pool (bf16 input)
    poolsegbf_kernel<<<(N_FUNC * 32 + 255) / 256, 256>>>(HB, fstart, pool, N_FUNC);

    // FCG layer (assemble fused into gather)
    gather128a_kernel<<<(N_FCG * 32 + 255) / 256, 256>>>(
        frowptr, fdeg, fcsr, pool, emb, fsrc, fext, fdis, fz, N_FCG);
    gemmx_kernel<128, false><<<(N_FCG + 127) / 128, 256>>>(fz, Wf, bf, fdis, fy, N_FCG);

    // binary-level mean pool + head
    gpool_kernel<<<NB, 128>>>(fy, bstart, gg);
    head_kernel<<<1, 256>>>(gg, Wp1, bp1, Wp2, bp2, Wp3, bp3, out);
}

// round 16
// speedup vs baseline: 1.1692x; 1.0083x over previous
#include <cuda_runtime.h>
#include <cuda_bf16.h>
#include <mma.h>
#include <math.h>

using namespace nvcuda;

#define N_CFG 400000
#define E_CFG 1600000
#define N_FUNC 8000
#define N_FCG 9600
#define E_FCG 80000
#define NB 8
#define D_H 128
#define VOCAB 10002
#define FULLMASK 0xffffffffu

// ---------------- scratch (device globals) ----------------------------------
__device__ float g_b [(size_t)N_CFG * D_H];
__device__ __nv_bfloat16 g_hb[(size_t)N_CFG * D_H];
__device__ __nv_bfloat16 g_wb1[64 * 128];
__device__ __nv_bfloat16 g_wb2[128 * 128];
__device__ int   g_deg[N_CFG];
__device__ float g_dis[N_CFG];
__device__ int   g_rowptr[N_CFG];
__device__ int   g_cursor[N_CFG];
__device__ int   g_csr[E_CFG];
__device__ int   g_fdeg[N_FCG];
__device__ float g_fdis[N_FCG];
__device__ int   g_frowptr[N_FCG];
__device__ int   g_fcursor[N_FCG];
__device__ int   g_fcsr[E_FCG];
__device__ int   g_bsum[512];
__device__ int   g_fstart[N_FUNC + 1];
__device__ int   g_bstart[NB + 1];
__device__ float g_pool[N_FUNC * D_H];
__device__ float g_fz [N_FCG * D_H];
__device__ float g_fy [N_FCG * D_H];
__device__ float g_g  [NB * D_H];

#define NBLK_CFG ((N_CFG + 1023) / 1024)   // 391
#define NBLK_FCG ((N_FCG + 1023) / 1024)   // 10
#define FBSUM 400

static __device__ __forceinline__ unsigned pack_bf2(float a, float b) {
    __nv_bfloat162 h = __float22bfloat162_rn(make_float2(a, b));
    return *reinterpret_cast<unsigned*>(&h);
}
static __device__ __forceinline__ float2 unpack_bf2(unsigned u) {
    return __bfloat1622float2(*reinterpret_cast<const __nv_bfloat162*>(&u));
}
static __device__ __forceinline__ unsigned hadd2u(unsigned a, unsigned b) {
    __nv_bfloat162 r = __hadd2(*reinterpret_cast<const __nv_bfloat162*>(&a),
                               *reinterpret_cast<const __nv_bfloat162*>(&b));
    return *reinterpret_cast<unsigned*>(&r);
}

// ---------------- init: zero degs + weight->bf16 ------------------------------
__global__ void init_kernel(const float* __restrict__ W1, const float* __restrict__ W2) {
    int i = blockIdx.x * blockDim.x + threadIdx.x;
    if (i < N_CFG) g_deg[i] = 0;
    if (i < N_FCG) g_fdeg[i] = 0;
    if (i < 64 * 128) g_wb1[i] = __float2bfloat16(W1[i]);
    if (i >= 64 * 128 && i < 64 * 128 + 128 * 128)
        g_wb2[i - 64 * 128] = __float2bfloat16(W2[i - 64 * 128]);
}
__global__ void deg_all_kernel(const int* __restrict__ cei, const int* __restrict__ fei) {
    int i = blockIdx.x * blockDim.x + threadIdx.x;
    if (i < E_CFG) {
        atomicAdd(&g_deg[cei[E_CFG + i]], 1);
    } else if (i < E_CFG + E_FCG) {
        atomicAdd(&g_fdeg[fei[E_FCG + (i - E_CFG)]], 1);
    }
}

// ---------------- CSR build (merged; dis fused) -------------------------------
__device__ __forceinline__ void scan_local_body(const int* cnt, int n, int* out,
                                                int* bsum, float* dis, int blk, int t) {
    __shared__ int s[256];
    int base = blk * 1024;
    int v[4], sum = 0;
#pragma unroll
    for (int j = 0; j < 4; j++) {
        int i = base + t * 4 + j;
        v[j] = (i < n) ? cnt[i] : 0;
        if (i < n) dis[i] = rsqrtf((float)v[j] + 1.0f);
        sum += v[j];
    }
    s[t] = sum;
    __syncthreads();
    for (int off = 1; off < 256; off <<= 1) {
        int x = (t >= off) ? s[t - off] : 0;
        __syncthreads();
        s[t] += x;
        __syncthreads();
    }
    if (t == 255) bsum[blk] = s[255];
    int run = (t > 0) ? s[t - 1] : 0;
#pragma unroll
    for (int j = 0; j < 4; j++) {
        int i = base + t * 4 + j;
        if (i < n) out[i] = run;
        run += v[j];
    }
}
__global__ void scan_local_all() {
    if (blockIdx.x < NBLK_CFG)
        scan_local_body(g_deg, N_CFG, g_rowptr, g_bsum, g_dis, blockIdx.x, threadIdx.x);
    else
        scan_local_body(g_fdeg, N_FCG, g_frowptr, g_bsum + FBSUM, g_fdis,
                        blockIdx.x - NBLK_CFG, threadIdx.x);
}
__global__ void scan_bsum_all() {
    __shared__ int s[512];
    int* bsum = (blockIdx.x == 0) ? g_bsum : g_bsum + FBSUM;
    int nb = (blockIdx.x == 0) ? NBLK_CFG : NBLK_FCG;
    int t = threadIdx.x;
    s[t] = (t < nb) ? bsum[t] : 0;
    __syncthreads();
    for (int off = 1; off < 512; off <<= 1) {
        int x = (t >= off) ? s[t - off] : 0;
        __syncthreads();
        s[t] += x;
        __syncthreads();
    }
    if (t < nb) bsum[t] = (t > 0) ? s[t - 1] : 0;
}
__global__ void scan_add_all(const int* __restrict__ n2f, const int* __restrict__ fbatch) {
    int i = blockIdx.x * blockDim.x + threadIdx.x;
    if (i < N_CFG) {
        int v = g_rowptr[i] + g_bsum[i >> 10];
        g_rowptr[i] = v;
        g_cursor[i] = v;
    } else if (i < N_CFG + N_FCG) {
        int j = i - N_CFG;
        int v = g_frowptr[j] + g_bsum[FBSUM + (j >> 10)];
        g_frowptr[j] = v;
        g_fcursor[j] = v;
    } else if (i <= N_CFG + N_FCG + N_FUNC) {
        int f = i - (N_CFG + N_FCG);
        int lo = 0, hi = N_CFG;
        while (lo < hi) {
            int mid = (lo + hi) >> 1;
            if (n2f[mid] < f) lo = mid + 1; else hi = mid;
        }
        g_fstart[f] = lo;
    } else if (i <= N_CFG + N_FCG + N_FUNC + 1 + NB) {
        int f = i - (N_CFG + N_FCG + N_FUNC + 1);
        int lo = 0, hi = N_FCG;
        while (lo < hi) {
            int mid = (lo + hi) >> 1;
            if (fbatch[mid] < f) lo = mid + 1; else hi = mid;
        }
        g_bstart[f] = lo;
    }
}
__global__ void fill_csr_all(const int* __restrict__ cei, const int* __restrict__ fei) {
    int i = blockIdx.x * blockDim.x + threadIdx.x;
    if (i < E_CFG) {
        int r = cei[i], c = cei[E_CFG + i];
        int slot = atomicAdd(&g_cursor[c], 1);
        g_csr[slot] = r;
    } else if (i < E_CFG + E_FCG) {
        int j = i - E_CFG;
        int r = fei[j], c = fei[E_FCG + j];
        int slot = atomicAdd(&g_fcursor[c], 1);
        g_fcsr[slot] = r;
    }
}

// ---------------- WMMA bf16 GEMM ---------------------------------------------
template<int K, bool SCALE, bool OUTBF16>
__global__ __launch_bounds__(256, 2) void gemmw_kernel(
    const __nv_bfloat16* __restrict__ X, const __nv_bfloat16* __restrict__ Wb,
    const float* __restrict__ bias, const float* __restrict__ dis,
    float* __restrict__ H, __nv_bfloat16* __restrict__ HB, int N) {
    constexpr int AP = 40;
    constexpr int WP = 136;
    __shared__ __nv_bfloat16 As[128 * AP];
    __shared__ __nv_bfloat16 Ws[32 * WP];
    __shared__ float Eb[8][16 * 20];
    __shared__ float Bs[128];

    const int tid = threadIdx.x;
    const int warp = tid >> 5, lane = tid & 31;
    const int wr = warp >> 2;
    const int wc = warp & 3;
    const int row0 = blockIdx.x * 128;

    if (tid < 128) Bs[tid] = bias[tid];

    wmma::fragment<wmma::accumulator, 16, 16, 16, float> acc[4][2];
#pragma unroll
    for (int i = 0; i < 4; i++)
#pragma unroll
        for (int j = 0; j < 2; j++) wmma::fill_fragment(acc[i][j], 0.0f);

    const unsigned* Xu = (const unsigned*)X;
    const unsigned* Wu = (const unsigned*)Wb;
    unsigned* Asu = (unsigned*)As;
    unsigned* Wsu = (unsigned*)Ws;

    for (int kc = 0; kc < K; kc += 32) {
#pragma unroll
        for (int i = tid; i < 128 * 16; i += 256) {
            int r = i >> 4, k2 = i & 15;
            Asu[r * (AP / 2) + k2] = Xu[(size_t)(row0 + r) * (K / 2) + (kc >> 1) + k2];
        }
#pragma unroll
        for (int i = tid; i < 32 * 64; i += 256) {
            int k = i >> 6, c2 = i & 63;
            Wsu[k * (WP / 2) + c2] = Wu[(size_t)(kc + k) * 64 + c2];
        }
        __syncthreads();
#pragma unroll
        for (int ks = 0; ks < 32; ks += 16) {
            wmma::fragment<wmma::matrix_a, 16, 16, 16, __nv_bfloat16, wmma::row_major> af[4];
            wmma::fragment<wmma::matrix_b, 16, 16, 16, __nv_bfloat16, wmma::row_major> bf[2];
#pragma unroll
            for (int i = 0; i < 4; i++)
                wmma::load_matrix_sync(af[i], &As[(wr * 64 + i * 16) * AP + ks], AP);
#pragma unroll
            for (int j = 0; j < 2; j++)
                wmma::load_matrix_sync(bf[j], &Ws[ks * WP + wc * 32 + j * 16], WP);
#pragma unroll
            for (int i = 0; i < 4; i++)
#pragma unroll
                for (int j = 0; j < 2; j++)
                    wmma::mma_sync(acc[i][j], af[i], bf[j], acc[i][j]);
        }
        __syncthreads();
    }

    const int r = lane >> 1, c8 = (lane & 1) * 8;
#pragma unroll
    for (int i = 0; i < 4; i++) {
#pragma unroll
        for (int j = 0; j < 2; j++) {
            wmma::store_matrix_sync(&Eb[warp][0], acc[i][j], 20, wmma::mem_row_major);
            __syncwarp();
            int gr = row0 + wr * 64 + i * 16 + r;
            int gc = wc * 32 + j * 16 + c8;
            float s = SCALE ? dis[gr] : 1.0f;
            float o[8];
#pragma unroll
            for (int q = 0; q < 8; q++)
                o[q] = fmaxf(Eb[warp][r * 20 + c8 + q] + Bs[gc + q], 0.0f) * s;
            if (OUTBF16) {
                uint4 pk;
                pk.x = pack_bf2(o[0], o[1]); pk.y = pack_bf2(o[2], o[3]);
                pk.z = pack_bf2(o[4], o[5]); pk.w = pack_bf2(o[6], o[7]);
                *(uint4*)&HB[(size_t)gr * 128 + gc] = pk;
            } else {
                *(float4*)&H[(size_t)gr * 128 + gc]     = make_float4(o[0], o[1], o[2], o[3]);
                *(float4*)&H[(size_t)gr * 128 + gc + 4] = make_float4(o[4], o[5], o[6], o[7]);
            }
            __syncwarp();
        }
    }
}

// ---------------- FFMA2 GEMM (fp32, FCG) --------------------------------------
template<int K, bool SCALE>
__global__ __launch_bounds__(256, 2) void gemmx_kernel(
    const float* __restrict__ X, const float* __restrict__ W,
    const float* __restrict__ bias, const float* __restrict__ dis,
    float* __restrict__ H, int N) {
    __shared__ float Xs[32 * 132];
    __shared__ float Ws[32 * 128];
    const int row0 = blockIdx.x * 128;
    const int tx = threadIdx.x & 15;
    const int ty = threadIdx.x >> 4;
    const int c0 = tx * 8, r0 = ty * 8;

    unsigned long long acc2[8][4];
#pragma unroll
    for (int r = 0; r < 8; r++)
#pragma unroll
        for (int j = 0; j < 4; j++) acc2[r][j] = 0ULL;

    for (int kc = 0; kc < K; kc += 32) {
#pragma unroll
        for (int i = threadIdx.x; i < 128 * 32; i += 256) {
            int k = i & 31, r = i >> 5;
            int gr = row0 + r;
            Xs[k * 132 + r] = (gr < N) ? X[(size_t)gr * K + kc + k] : 0.f;
        }
#pragma unroll
        for (int i = threadIdx.x; i < 32 * 128; i += 256) {
            int c = i & 127, k = i >> 7;
            Ws[k * 128 + c] = W[(size_t)(kc + k) * 128 + c];
        }
        __syncthreads();
#pragma unroll 4
        for (int k = 0; k < 32; k++) {
            float4 al = *(const float4*)&Xs[k * 132 + r0];
            float4 ah = *(const float4*)&Xs[k * 132 + r0 + 4];
            ulonglong2 wl = *(const ulonglong2*)&Ws[k * 128 + c0];
            ulonglong2 wh = *(const ulonglong2*)&Ws[k * 128 + c0 + 4];
            unsigned long long w2[4];
            w2[0] = wl.x; w2[1] = wl.y; w2[2] = wh.x; w2[3] = wh.y;
            float a[8];
            a[0] = al.x; a[1] = al.y; a[2] = al.z; a[3] = al.w;
            a[4] = ah.x; a[5] = ah.y; a[6] = ah.z; a[7] = ah.w;
#pragma unroll
            for (int r = 0; r < 8; r++) {
                unsigned long long a2;
                asm("mov.b64 %0, {%1, %1};" : "=l"(a2) : "f"(a[r]));
#pragma unroll
                for (int j = 0; j < 4; j++)
                    asm("fma.rn.f32x2 %0, %1, %2, %0;"
                        : "+l"(acc2[r][j]) : "l"(a2), "l"(w2[j]));
            }
        }
        __syncthreads();
    }

    float bb[8];
#pragma unroll
    for (int j = 0; j < 8; j++) bb[j] = bias[c0 + j];
#pragma unroll
    for (int r = 0; r < 8; r++) {
        int gr = row0 + r0 + r;
        if (gr >= N) return;
        float s = SCALE ? dis[gr] : 1.0f;
        float o[8];
#pragma unroll
        for (int j = 0; j < 4; j++) {
            float lo, hi;
            asm("mov.b64 {%0, %1}, %2;" : "=f"(lo), "=f"(hi) : "l"(acc2[r][j]));
            o[2 * j]     = fmaxf(lo + bb[2 * j], 0.f) * s;
            o[2 * j + 1] = fmaxf(hi + bb[2 * j + 1], 0.f) * s;
        }
        *(float4*)&H[(size_t)gr * 128 + c0]     = make_float4(o[0], o[1], o[2], o[3]);
        *(float4*)&H[(size_t)gr * 128 + c0 + 4] = make_float4(o[4], o[5], o[6], o[7]);
    }
}

// ---------------- gather 64ch direct from fp32 cfg_x (tobf fused) -------------
__global__ __launch_bounds__(256) void gather64f_kernel(
    const int* __restrict__ rowptr, const int* __restrict__ deg,
    const int* __restrict__ csr, const float4* __restrict__ x,
    const float* __restrict__ dis, uint4* __restrict__ out, int n) {
    int lane = threadIdx.x & 31;
    int q = lane >> 3;
    int sub = lane & 7;
    int node = ((blockIdx.x * 256 + threadIdx.x) >> 5) * 4 + q;
    if (node >= n) return;
    int start = rowptr[node], d = deg[node];
    int dm = min(d, 8);
    int uidx = (sub < dm) ? csr[start + sub] : 0;
    int u[8];
#pragma unroll
    for (int j = 0; j < 8; j++) u[j] = __shfl_sync(FULLMASK, uidx, (q << 3) + j);
    float dn = dis[node];
    float a[8];
    {
        float4 s0 = x[(size_t)node * 16 + sub * 2];
        float4 s1 = x[(size_t)node * 16 + sub * 2 + 1];
        a[0] = s0.x * dn; a[1] = s0.y * dn; a[2] = s0.z * dn; a[3] = s0.w * dn;
        a[4] = s1.x * dn; a[5] = s1.y * dn; a[6] = s1.z * dn; a[7] = s1.w * dn;
    }
#pragma unroll
    for (int j = 0; j < 8; j++) {
        if (j < dm) {
            float du = dis[u[j]];
            float4 r0 = x[(size_t)u[j] * 16 + sub * 2];
            float4 r1 = x[(size_t)u[j] * 16 + sub * 2 + 1];
            a[0] += r0.x * du; a[1] += r0.y * du; a[2] += r0.z * du; a[3] += r0.w * du;
            a[4] += r1.x * du; a[5] += r1.y * du; a[6] += r1.z * du; a[7] += r1.w * du;
        }
    }
    for (int e = 8; e < d; e++) {
        int uu = csr[start + e];
        float du = dis[uu];
        float4 r0 = x[(size_t)uu * 16 + sub * 2];
        float4 r1 = x[(size_t)uu * 16 + sub * 2 + 1];
        a[0] += r0.x * du; a[1] += r0.y * du; a[2] += r0.z * du; a[3] += r0.w * du;
        a[4] += r1.x * du; a[5] += r1.y * du; a[6] += r1.z * du; a[7] += r1.w * du;
    }
    uint4 pk;
    pk.x = pack_bf2(a[0] * dn, a[1] * dn);
    pk.y = pack_bf2(a[2] * dn, a[3] * dn);
    pk.z = pack_bf2(a[4] * dn, a[5] * dn);
    pk.w = pack_bf2(a[6] * dn, a[7] * dn);
    out[(size_t)node * 8 + sub] = pk;
}

// ---------------- gather 128ch bf16, PACKED HADD2 accumulation ----------------
__global__ __launch_bounds__(256) void gather128bf_kernel(
    const int* __restrict__ rowptr, const int* __restrict__ deg,
    const int* __restrict__ csr, const __nv_bfloat16* __restrict__ hb,
    const float* __restrict__ dis, uint4* __restrict__ out, int n) {
    int lane = threadIdx.x & 31;
    int q = lane >> 3;
    int sub = lane & 7;
    int node = ((blockIdx.x * 256 + threadIdx.x) >> 5) * 4 + q;
    if (node >= n) return;
    const uint4* h16 = (const uint4*)hb;
    int start = rowptr[node], d = deg[node];
    int dm = min(d, 8);
    int uidx = (sub < dm) ? csr[start + sub] : 0;
    int u[8];
#pragma unroll
    for (int j = 0; j < 8; j++) u[j] = __shfl_sync(FULLMASK, uidx, (q << 3) + j);
    unsigned acc[8];
    {
        uint4 r0 = h16[(size_t)node * 16 + sub];
        uint4 r1 = h16[(size_t)node * 16 + 8 + sub];
        acc[0] = r0.x; acc[1] = r0.y; acc[2] = r0.z; acc[3] = r0.w;
        acc[4] = r1.x; acc[5] = r1.y; acc[6] = r1.z; acc[7] = r1.w;
    }
#pragma unroll
    for (int j = 0; j < 8; j++) {
        if (j < dm) {
            uint4 r0 = h16[(size_t)u[j] * 16 + sub];
            uint4 r1 = h16[(size_t)u[j] * 16 + 8 + sub];
            acc[0] = hadd2u(acc[0], r0.x); acc[1] = hadd2u(acc[1], r0.y);
            acc[2] = hadd2u(acc[2], r0.z); acc[3] = hadd2u(acc[3], r0.w);
            acc[4] = hadd2u(acc[4], r1.x); acc[5] = hadd2u(acc[5], r1.y);
            acc[6] = hadd2u(acc[6], r1.z); acc[7] = hadd2u(acc[7], r1.w);
        }
    }
    for (int e = 8; e < d; e++) {
        int uu = csr[start + e];
        uint4 r0 = h16[(size_t)uu * 16 + sub];
        uint4 r1 = h16[(size_t)uu * 16 + 8 + sub];
        acc[0] = hadd2u(acc[0], r0.x); acc[1] = hadd2u(acc[1], r0.y);
        acc[2] = hadd2u(acc[2], r0.z); acc[3] = hadd2u(acc[3], r0.w);
        acc[4] = hadd2u(acc[4], r1.x); acc[5] = hadd2u(acc[5], r1.y);
        acc[6] = hadd2u(acc[6], r1.z); acc[7] = hadd2u(acc[7], r1.w);
    }
    float dn = dis[node];
    uint4 pk0, pk1;
    {
        float2 f0 = unpack_bf2(acc[0]), f1 = unpack_bf2(acc[1]);
        float2 f2 = unpack_bf2(acc[2]), f3 = unpack_bf2(acc[3]);
        float2 g0 = unpack_bf2(acc[4]), g1 = unpack_bf2(acc[5]);
        float2 g2 = unpack_bf2(acc[6]), g3 = unpack_bf2(acc[7]);
        pk0.x = pack_bf2(f0.x * dn, f0.y * dn);
        pk0.y = pack_bf2(f1.x * dn, f1.y * dn);
        pk0.z = pack_bf2(f2.x * dn, f2.y * dn);
        pk0.w = pack_bf2(f3.x * dn, f3.y * dn);
        pk1.x = pack_bf2(g0.x * dn, g0.y * dn);
        pk1.y = pack_bf2(g1.x * dn, g1.y * dn);
        pk1.z = pack_bf2(g2.x * dn, g2.y * dn);
        pk1.w = pack_bf2(g3.x * dn, g3.y * dn);
    }
    out[(size_t)node * 16 + sub] = pk0;
    out[(size_t)node * 16 + 8 + sub] = pk1;
}

// ---------------- FCG gather with assemble fused ------------------------------
static __device__ __forceinline__ float4 fcg_row(
    const float4* __restrict__ pool4, const float4* __restrict__ emb4,
    const int* __restrict__ src, const int* __restrict__ isext, int i, int lane) {
    int s = src[i];
    if (isext[i] == 1) {
        int k = min(max(s, 0), VOCAB - 1);
        return emb4[(size_t)k * 32 + lane];
    } else {
        int k = min(max(s, 0), N_FUNC - 1);
        return pool4[(size_t)k * 32 + lane];
    }
}
__global__ __launch_bounds__(256) void gather128a_kernel(
    const int* __restrict__ rowptr, const int* __restrict__ deg,
    const int* __restrict__ csr,
    const float* __restrict__ pool, const float* __restrict__ emb,
    const int* __restrict__ src, const int* __restrict__ isext,
    const float* __restrict__ dis, float* __restrict__ out, int n) {
    int node = (blockIdx.x * 256 + threadIdx.x) >> 5;
    int lane = threadIdx.x & 31;
    if (node >= n) return;
    const float4* pool4 = (const float4*)pool;
    const float4* emb4 = (const float4*)emb;
    int start = rowptr[node], d = deg[node];
    int dm = min(d, 32);
    int uidx = (lane < dm) ? csr[start + lane] : 0;
    float dn = dis[node];
    float4 acc = fcg_row(pool4, emb4, src, isext, node, lane);
    acc.x *= dn; acc.y *= dn; acc.z *= dn; acc.w *= dn;
    for (int e = 0; e < dm; e++) {
        int u = __shfl_sync(FULLMASK, uidx, e);
        float du = dis[u];
        float4 v = fcg_row(pool4, emb4, src, isext, u, lane);
        acc.x += v.x * du; acc.y += v.y * du;
        acc.z += v.z * du; acc.w += v.w * du;
    }
    for (int e = 32; e < d; e++) {
        int u = csr[start + e];
        float du = dis[u];
        float4 v = fcg_row(pool4, emb4, src, isext, u, lane);
        acc.x += v.x * du; acc.y += v.y * du;
        acc.z += v.z * du; acc.w += v.w * du;
    }
    acc.x *= dn; acc.y *= dn; acc.z *= dn; acc.w *= dn;
    ((float4*)out)[(size_t)node * 32 + lane] = acc;
}

// ---------------- function-level mean pool (bf16 input) -----------------------
__global__ __launch_bounds__(256) void poolsegbf_kernel(
    const __nv_bfloat16* __restrict__ x, const int* __restrict__ start,
    float* __restrict__ pool, int nseg) {
    int f = (blockIdx.x * 256 + threadIdx.x) >> 5;
    int lane = threadIdx.x & 31;
    if (f >= nseg) return;
    int s = start[f], e = start[f + 1];
    const uint2* x8 = (const uint2*)x;
    float a0 = 0.f, a1 = 0.f, a2 = 0.f, a3 = 0.f;
    for (int i = s; i < e; i++) {
        uint2 raw = x8[(size_t)i * 32 + lane];
        float2 f0 = unpack_bf2(raw.x), f1 = unpack_bf2(raw.y);
        a0 += f0.x; a1 += f0.y; a2 += f1.x; a3 += f1.y;
    }
    float inv = 1.0f / (float)max(e - s, 1);
    ((float4*)pool)[(size_t)f * 32 + lane] = make_float4(a0 * inv, a1 * inv, a2 * inv, a3 * inv);
}

__global__ __launch_bounds__(128) void gpool_kernel(
    const float* __restrict__ y, const int* __restrict__ start, float* __restrict__ g) {
    int b = blockIdx.x, col = threadIdx.x;
    int s = start[b], e = start[b + 1];
    float acc = 0.f;
    for (int i = s; i < e; i++) acc += y[(size_t)i * 128 + col];
    g[b * 128 + col] = acc / (float)max(e - s, 1);
}

__global__ __launch_bounds__(256) void head_kernel(
    const float* __restrict__ g,
    const float* __restrict__ Wp1, const float* __restrict__ bp1,
    const float* __restrict__ Wp2, const float* __restrict__ bp2,
    const float* __restrict__ Wp3, const float* __restrict__ bp3,
    float* __restrict__ out) {
    __shared__ float G[NB * 128], H1[NB * 64], H2[NB * 32];
    int t = threadIdx.x;
    for (int i = t; i < NB * 128; i += 256) G[i] = g[i];
    __syncthreads();
    for (int i = t; i < NB * 64; i += 256) {
        int r = i >> 6, c = i & 63;
        float a = bp1[c];
        for (int k = 0; k < 128; k++) a += G[r * 128 + k] * Wp1[k * 64 + c];
        H1[i] = fmaxf(a, 0.f);
    }
    __syncthreads();
    for (int i = t; i < NB * 32; i += 256) {
        int r = i >> 5, c = i & 31;
        float a = bp2[c];
        for (int k = 0; k < 64; k++) a += H1[r * 64 + k] * Wp2[k * 32 + c];
        H2[i] = fmaxf(a, 0.f);
    }
    __syncthreads();
    if (t < NB) {
        float a = bp3[0];
        for (int k = 0; k < 32; k++) a += H2[t * 32 + k] * Wp3[k];
        out[t] = 1.0f / (1.0f + expf(-a));
    }
}

// ---------------- launch ----------------------------------------------------
extern "C" void kernel_launch(void* const* d_in, const int* in_sizes, int n_in,
                              void* d_out, int out_size) {
    const float* cfg_x  = (const float*)d_in[0];
    const int*   cfg_ei = (const int*)  d_in[1];
    const int*   n2f    = (const int*)  d_in[2];
    const int*   fcg_ei = (const int*)  d_in[3];
    const int*   fbatch = (const int*)  d_in[4];
    const int*   fsrc   = (const int*)  d_in[5];
    const int*   fext   = (const int*)  d_in[6];
    const float* W1  = (const float*)d_in[7];
    const float* b1  = (const float*)d_in[8];
    const float* W2  = (const float*)d_in[9];
    const float* b2  = (const float*)d_in[10];
    const float* emb = (const float*)d_in[11];
    const float* Wf  = (const float*)d_in[12];
    const float* bf  = (const float*)d_in[13];
    const float* Wp1 = (const float*)d_in[14];
    const float* bp1 = (const float*)d_in[15];
    const float* Wp2 = (const float*)d_in[16];
    const float* bp2 = (const float*)d_in[17];
    const float* Wp3 = (const float*)d_in[18];
    const float* bp3 = (const float*)d_in[19];
    float* out = (float*)d_out;

    void *p;
    cudaGetSymbolAddress(&p, g_b);       float* Bb     = (float*)p;
    cudaGetSymbolAddress(&p, g_hb);      __nv_bfloat16* HB = (__nv_bfloat16*)p;
    cudaGetSymbolAddress(&p, g_wb1);     __nv_bfloat16* Wb1 = (__nv_bfloat16*)p;
    cudaGetSymbolAddress(&p, g_wb2);     __nv_bfloat16* Wb2 = (__nv_bfloat16*)p;
    cudaGetSymbolAddress(&p, g_deg);     int*   deg    = (int*)p;
    cudaGetSymbolAddress(&p, g_dis);     float* dis    = (float*)p;
    cudaGetSymbolAddress(&p, g_rowptr);  int*   rowptr = (int*)p;
    cudaGetSymbolAddress(&p, g_csr);     int*   csr    = (int*)p;
    cudaGetSymbolAddress(&p, g_fdeg);    int*   fdeg   = (int*)p;
    cudaGetSymbolAddress(&p, g_fdis);    float* fdis   = (float*)p;
    cudaGetSymbolAddress(&p, g_frowptr); int*   frowptr= (int*)p;
    cudaGetSymbolAddress(&p, g_fcsr);    int*   fcsr   = (int*)p;
    cudaGetSymbolAddress(&p, g_fstart);  int*   fstart = (int*)p;
    cudaGetSymbolAddress(&p, g_bstart);  int*   bstart = (int*)p;
    cudaGetSymbolAddress(&p, g_pool);    float* pool   = (float*)p;
    cudaGetSymbolAddress(&p, g_fz);      float* fz     = (float*)p;
    cudaGetSymbolAddress(&p, g_fy);      float* fy     = (float*)p;
    cudaGetSymbolAddress(&p, g_g);       float* gg     = (float*)p;

    unsigned* z1b = (unsigned*)Bb;                   // gather1 out, 64ch bf16
    uint4*    z2b = (uint4*)Bb + (size_t)N_CFG * 8;  // gather2 out, 128ch bf16

    // prolog: init + degrees (dis fused into scan)
    init_kernel<<<(N_CFG + 255) / 256, 256>>>(W1, W2);
    deg_all_kernel<<<(E_CFG + E_FCG + 255) / 256, 256>>>(cfg_ei, fcg_ei);

    // CSR build (merged; dis in scan_local; bounds in scan_add)
    scan_local_all<<<NBLK_CFG + NBLK_FCG, 256>>>();
    scan_bsum_all<<<2, 512>>>();
    scan_add_all<<<(N_CFG + N_FCG + N_FUNC + NB + 2 + 255) / 256, 256>>>(n2f, fbatch);
    fill_csr_all<<<(E_CFG + E_FCG + 255) / 256, 256>>>(cfg_ei, fcg_ei);

    // CFG layer 1 (direct fp32 gather, tobf fused)
    gather64f_kernel<<<(N_CFG + 31) / 32, 256>>>(rowptr, deg, csr,
                                                 (const float4*)cfg_x, dis, (uint4*)z1b, N_CFG);
    gemmw_kernel<64, true, true><<<N_CFG / 128, 256>>>(
        (const __nv_bfloat16*)z1b, Wb1, b1, dis, nullptr, HB, N_CFG);

    // CFG layer 2 (packed bf16 HADD2 accumulation in gather)
    gather128bf_kernel<<<(N_CFG + 31) / 32, 256>>>(rowptr, deg, csr, HB, dis, z2b, N_CFG);
    gemmw_kernel<128, false, true><<<N_CFG / 128, 256>>>(
        (const __nv_bfloat16*)z2b, Wb2, b2, dis, nullptr, HB, N_CFG);

    // function-level mean pool (bf16 input)
    poolsegbf_kernel<<<(N_FUNC * 32 + 255) / 256, 256>>>(HB, fstart, pool, N_FUNC);

    // FCG layer (assemble fused into gather)
    gather128a_kernel<<<(N_FCG * 32 + 255) / 256, 256>>>(
        frowptr, fdeg, fcsr, pool, emb, fsrc, fext, fdis, fz, N_FCG);
    gemmx_kernel<128, false><<<(N_FCG + 127) / 128, 256>>>(fz, Wf, bf, fdis, fy, N_FCG);

    // binary-level mean pool + head
    gpool_kernel<<<NB, 128>>>(fy, bstart, gg);
    head_kernel<<<1, 256>>>(gg, Wp1, bp1, Wp2, bp2, Wp3, bp3, out);
}

// round 17
// speedup vs baseline: 1.2016x; 1.0276x over previous
#include <cuda_runtime.h>
#include <cuda_bf16.h>
#include <mma.h>
#include <math.h>

using namespace nvcuda;

#define N_CFG 400000
#define E_CFG 1600000
#define N_FUNC 8000
#define N_FCG 9600
#define E_FCG 80000
#define NB 8
#define D_H 128
#define VOCAB 10002
#define FULLMASK 0xffffffffu

// ---------------- scratch (device globals) ----------------------------------
__device__ float g_b [(size_t)N_CFG * D_H];
__device__ __nv_bfloat16 g_hb[(size_t)N_CFG * D_H];
__device__ __nv_bfloat16 g_wb1[64 * 128];
__device__ __nv_bfloat16 g_wb2[128 * 128];
__device__ int   g_deg[N_CFG];
__device__ float g_dis[N_CFG];
__device__ int   g_rowptr[N_CFG];
__device__ int   g_cursor[N_CFG];
__device__ int   g_csr[E_CFG];
__device__ int   g_fdeg[N_FCG];
__device__ float g_fdis[N_FCG];
__device__ int   g_frowptr[N_FCG];
__device__ int   g_fcursor[N_FCG];
__device__ int   g_fcsr[E_FCG];
__device__ int   g_bsum[512];
__device__ int   g_fstart[N_FUNC + 1];
__device__ int   g_bstart[NB + 1];
__device__ float g_pool[N_FUNC * D_H];
__device__ float g_fz [N_FCG * D_H];
__device__ float g_fy [N_FCG * D_H];
__device__ float g_g  [NB * D_H];

#define NBLK_CFG ((N_CFG + 1023) / 1024)   // 391
#define NBLK_FCG ((N_FCG + 1023) / 1024)   // 10
#define FBSUM 400

static __device__ __forceinline__ unsigned pack_bf2(float a, float b) {
    __nv_bfloat162 h = __float22bfloat162_rn(make_float2(a, b));
    return *reinterpret_cast<unsigned*>(&h);
}
static __device__ __forceinline__ float2 unpack_bf2(unsigned u) {
    return __bfloat1622float2(*reinterpret_cast<const __nv_bfloat162*>(&u));
}
static __device__ __forceinline__ unsigned hadd2u(unsigned a, unsigned b) {
    __nv_bfloat162 r = __hadd2(*reinterpret_cast<const __nv_bfloat162*>(&a),
                               *reinterpret_cast<const __nv_bfloat162*>(&b));
    return *reinterpret_cast<unsigned*>(&r);
}

// ---------------- init: zero degs + weight->bf16 ------------------------------
__global__ void init_kernel(const float* __restrict__ W1, const float* __restrict__ W2) {
    int i = blockIdx.x * blockDim.x + threadIdx.x;
    if (i < N_CFG) g_deg[i] = 0;
    if (i < N_FCG) g_fdeg[i] = 0;
    if (i < 64 * 128) g_wb1[i] = __float2bfloat16(W1[i]);
    if (i >= 64 * 128 && i < 64 * 128 + 128 * 128)
        g_wb2[i - 64 * 128] = __float2bfloat16(W2[i - 64 * 128]);
}
__global__ void deg_all_kernel(const int* __restrict__ cei, const int* __restrict__ fei) {
    int i = blockIdx.x * blockDim.x + threadIdx.x;
    if (i < E_CFG) {
        atomicAdd(&g_deg[cei[E_CFG + i]], 1);
    } else if (i < E_CFG + E_FCG) {
        atomicAdd(&g_fdeg[fei[E_FCG + (i - E_CFG)]], 1);
    }
}

// ---------------- CSR build (merged; dis fused) -------------------------------
__device__ __forceinline__ void scan_local_body(const int* cnt, int n, int* out,
                                                int* bsum, float* dis, int blk, int t) {
    __shared__ int s[256];
    int base = blk * 1024;
    int v[4], sum = 0;
#pragma unroll
    for (int j = 0; j < 4; j++) {
        int i = base + t * 4 + j;
        v[j] = (i < n) ? cnt[i] : 0;
        if (i < n) dis[i] = rsqrtf((float)v[j] + 1.0f);
        sum += v[j];
    }
    s[t] = sum;
    __syncthreads();
    for (int off = 1; off < 256; off <<= 1) {
        int x = (t >= off) ? s[t - off] : 0;
        __syncthreads();
        s[t] += x;
        __syncthreads();
    }
    if (t == 255) bsum[blk] = s[255];
    int run = (t > 0) ? s[t - 1] : 0;
#pragma unroll
    for (int j = 0; j < 4; j++) {
        int i = base + t * 4 + j;
        if (i < n) out[i] = run;
        run += v[j];
    }
}
__global__ void scan_local_all() {
    if (blockIdx.x < NBLK_CFG)
        scan_local_body(g_deg, N_CFG, g_rowptr, g_bsum, g_dis, blockIdx.x, threadIdx.x);
    else
        scan_local_body(g_fdeg, N_FCG, g_frowptr, g_bsum + FBSUM, g_fdis,
                        blockIdx.x - NBLK_CFG, threadIdx.x);
}
__global__ void scan_bsum_all() {
    __shared__ int s[512];
    int* bsum = (blockIdx.x == 0) ? g_bsum : g_bsum + FBSUM;
    int nb = (blockIdx.x == 0) ? NBLK_CFG : NBLK_FCG;
    int t = threadIdx.x;
    s[t] = (t < nb) ? bsum[t] : 0;
    __syncthreads();
    for (int off = 1; off < 512; off <<= 1) {
        int x = (t >= off) ? s[t - off] : 0;
        __syncthreads();
        s[t] += x;
        __syncthreads();
    }
    if (t < nb) bsum[t] = (t > 0) ? s[t - 1] : 0;
}
__global__ void scan_add_all(const int* __restrict__ n2f, const int* __restrict__ fbatch) {
    int i = blockIdx.x * blockDim.x + threadIdx.x;
    if (i < N_CFG) {
        int v = g_rowptr[i] + g_bsum[i >> 10];
        g_rowptr[i] = v;
        g_cursor[i] = v;
    } else if (i < N_CFG + N_FCG) {
        int j = i - N_CFG;
        int v = g_frowptr[j] + g_bsum[FBSUM + (j >> 10)];
        g_frowptr[j] = v;
        g_fcursor[j] = v;
    } else if (i <= N_CFG + N_FCG + N_FUNC) {
        int f = i - (N_CFG + N_FCG);
        int lo = 0, hi = N_CFG;
        while (lo < hi) {
            int mid = (lo + hi) >> 1;
            if (n2f[mid] < f) lo = mid + 1; else hi = mid;
        }
        g_fstart[f] = lo;
    } else if (i <= N_CFG + N_FCG + N_FUNC + 1 + NB) {
        int f = i - (N_CFG + N_FCG + N_FUNC + 1);
        int lo = 0, hi = N_FCG;
        while (lo < hi) {
            int mid = (lo + hi) >> 1;
            if (fbatch[mid] < f) lo = mid + 1; else hi = mid;
        }
        g_bstart[f] = lo;
    }
}
__global__ void fill_csr_all(const int* __restrict__ cei, const int* __restrict__ fei) {
    int i = blockIdx.x * blockDim.x + threadIdx.x;
    if (i < E_CFG) {
        int r = cei[i], c = cei[E_CFG + i];
        int slot = atomicAdd(&g_cursor[c], 1);
        g_csr[slot] = r;
    } else if (i < E_CFG + E_FCG) {
        int j = i - E_CFG;
        int r = fei[j], c = fei[E_FCG + j];
        int slot = atomicAdd(&g_fcursor[c], 1);
        g_fcsr[slot] = r;
    }
}

// ---------------- WMMA bf16 GEMM — FULL-K single-stage ------------------------
// Stage all of As [128,K] and Ws [K,128] into (dynamic) smem once, one sync,
// then an uninterrupted MMA run. K=64: 46.5KB; K=128: 80.3KB (occupancy 2).
template<int K, bool SCALE, bool OUTBF16>
__global__ __launch_bounds__(256) void gemmw_kernel(
    const __nv_bfloat16* __restrict__ X, const __nv_bfloat16* __restrict__ Wb,
    const float* __restrict__ bias, const float* __restrict__ dis,
    float* __restrict__ H, __nv_bfloat16* __restrict__ HB, int N) {
    constexpr int AP = K + 8;
    constexpr int WP = 136;
    extern __shared__ char smem[];
    __nv_bfloat16* As = (__nv_bfloat16*)smem;                           // 128*AP
    __nv_bfloat16* Ws = (__nv_bfloat16*)(smem + 128 * AP * 2);          // K*WP
    float* Eb = (float*)(smem + 128 * AP * 2 + (size_t)K * WP * 2);     // 8*320
    float* Bs = Eb + 8 * 320;                                           // 128

    const int tid = threadIdx.x;
    const int warp = tid >> 5, lane = tid & 31;
    const int wr = warp >> 2;
    const int wc = warp & 3;
    const int row0 = blockIdx.x * 128;

    if (tid < 128) Bs[tid] = bias[tid];

    const unsigned* Xu = (const unsigned*)X;
    const unsigned* Wu = (const unsigned*)Wb;
    unsigned* Asu = (unsigned*)As;
    unsigned* Wsu = (unsigned*)Ws;

    // stage everything once
#pragma unroll
    for (int i = tid; i < 128 * (K / 2); i += 256) {
        int r = i / (K / 2), k2 = i % (K / 2);
        Asu[r * (AP / 2) + k2] = Xu[(size_t)(row0 + r) * (K / 2) + k2];
    }
#pragma unroll
    for (int i = tid; i < K * 64; i += 256) {
        int k = i >> 6, c2 = i & 63;
        Wsu[k * (WP / 2) + c2] = Wu[(size_t)k * 64 + c2];
    }
    __syncthreads();

    wmma::fragment<wmma::accumulator, 16, 16, 16, float> acc[4][2];
#pragma unroll
    for (int i = 0; i < 4; i++)
#pragma unroll
        for (int j = 0; j < 2; j++) wmma::fill_fragment(acc[i][j], 0.0f);

#pragma unroll
    for (int ks = 0; ks < K; ks += 16) {
        wmma::fragment<wmma::matrix_a, 16, 16, 16, __nv_bfloat16, wmma::row_major> af[4];
        wmma::fragment<wmma::matrix_b, 16, 16, 16, __nv_bfloat16, wmma::row_major> bf[2];
#pragma unroll
        for (int i = 0; i < 4; i++)
            wmma::load_matrix_sync(af[i], &As[(wr * 64 + i * 16) * AP + ks], AP);
#pragma unroll
        for (int j = 0; j < 2; j++)
            wmma::load_matrix_sync(bf[j], &Ws[ks * WP + wc * 32 + j * 16], WP);
#pragma unroll
        for (int i = 0; i < 4; i++)
#pragma unroll
            for (int j = 0; j < 2; j++)
                wmma::mma_sync(acc[i][j], af[i], bf[j], acc[i][j]);
    }

    // epilogue (per-warp Eb buffer; no cross-warp dependency)
    const int r = lane >> 1, c8 = (lane & 1) * 8;
    float* myEb = Eb + warp * 320;
#pragma unroll
    for (int i = 0; i < 4; i++) {
#pragma unroll
        for (int j = 0; j < 2; j++) {
            wmma::store_matrix_sync(myEb, acc[i][j], 20, wmma::mem_row_major);
            __syncwarp();
            int gr = row0 + wr * 64 + i * 16 + r;
            int gc = wc * 32 + j * 16 + c8;
            float s = SCALE ? dis[gr] : 1.0f;
            float o[8];
#pragma unroll
            for (int q = 0; q < 8; q++)
                o[q] = fmaxf(myEb[r * 20 + c8 + q] + Bs[gc + q], 0.0f) * s;
            if (OUTBF16) {
                uint4 pk;
                pk.x = pack_bf2(o[0], o[1]); pk.y = pack_bf2(o[2], o[3]);
                pk.z = pack_bf2(o[4], o[5]); pk.w = pack_bf2(o[6], o[7]);
                *(uint4*)&HB[(size_t)gr * 128 + gc] = pk;
            } else {
                *(float4*)&H[(size_t)gr * 128 + gc]     = make_float4(o[0], o[1], o[2], o[3]);
                *(float4*)&H[(size_t)gr * 128 + gc + 4] = make_float4(o[4], o[5], o[6], o[7]);
            }
            __syncwarp();
        }
    }
}

// ---------------- FFMA2 GEMM (fp32, FCG) --------------------------------------
template<int K, bool SCALE>
__global__ __launch_bounds__(256, 2) void gemmx_kernel(
    const float* __restrict__ X, const float* __restrict__ W,
    const float* __restrict__ bias, const float* __restrict__ dis,
    float* __restrict__ H, int N) {
    __shared__ float Xs[32 * 132];
    __shared__ float Ws[32 * 128];
    const int row0 = blockIdx.x * 128;
    const int tx = threadIdx.x & 15;
    const int ty = threadIdx.x >> 4;
    const int c0 = tx * 8, r0 = ty * 8;

    unsigned long long acc2[8][4];
#pragma unroll
    for (int r = 0; r < 8; r++)
#pragma unroll
        for (int j = 0; j < 4; j++) acc2[r][j] = 0ULL;

    for (int kc = 0; kc < K; kc += 32) {
#pragma unroll
        for (int i = threadIdx.x; i < 128 * 32; i += 256) {
            int k = i & 31, r = i >> 5;
            int gr = row0 + r;
            Xs[k * 132 + r] = (gr < N) ? X[(size_t)gr * K + kc + k] : 0.f;
        }
#pragma unroll
        for (int i = threadIdx.x; i < 32 * 128; i += 256) {
            int c = i & 127, k = i >> 7;
            Ws[k * 128 + c] = W[(size_t)(kc + k) * 128 + c];
        }
        __syncthreads();
#pragma unroll 4
        for (int k = 0; k < 32; k++) {
            float4 al = *(const float4*)&Xs[k * 132 + r0];
            float4 ah = *(const float4*)&Xs[k * 132 + r0 + 4];
            ulonglong2 wl = *(const ulonglong2*)&Ws[k * 128 + c0];
            ulonglong2 wh = *(const ulonglong2*)&Ws[k * 128 + c0 + 4];
            unsigned long long w2[4];
            w2[0] = wl.x; w2[1] = wl.y; w2[2] = wh.x; w2[3] = wh.y;
            float a[8];
            a[0] = al.x; a[1] = al.y; a[2] = al.z; a[3] = al.w;
            a[4] = ah.x; a[5] = ah.y; a[6] = ah.z; a[7] = ah.w;
#pragma unroll
            for (int r = 0; r < 8; r++) {
                unsigned long long a2;
                asm("mov.b64 %0, {%1, %1};" : "=l"(a2) : "f"(a[r]));
#pragma unroll
                for (int j = 0; j < 4; j++)
                    asm("fma.rn.f32x2 %0, %1, %2, %0;"
                        : "+l"(acc2[r][j]) : "l"(a2), "l"(w2[j]));
            }
        }
        __syncthreads();
    }

    float bb[8];
#pragma unroll
    for (int j = 0; j < 8; j++) bb[j] = bias[c0 + j];
#pragma unroll
    for (int r = 0; r < 8; r++) {
        int gr = row0 + r0 + r;
        if (gr >= N) return;
        float s = SCALE ? dis[gr] : 1.0f;
        float o[8];
#pragma unroll
        for (int j = 0; j < 4; j++) {
            float lo, hi;
            asm("mov.b64 {%0, %1}, %2;" : "=f"(lo), "=f"(hi) : "l"(acc2[r][j]));
            o[2 * j]     = fmaxf(lo + bb[2 * j], 0.f) * s;
            o[2 * j + 1] = fmaxf(hi + bb[2 * j + 1], 0.f) * s;
        }
        *(float4*)&H[(size_t)gr * 128 + c0]     = make_float4(o[0], o[1], o[2], o[3]);
        *(float4*)&H[(size_t)gr * 128 + c0 + 4] = make_float4(o[4], o[5], o[6], o[7]);
    }
}

// ---------------- gather 64ch direct from fp32 cfg_x (tobf fused) -------------
__global__ __launch_bounds__(256) void gather64f_kernel(
    const int* __restrict__ rowptr, const int* __restrict__ deg,
    const int* __restrict__ csr, const float4* __restrict__ x,
    const float* __restrict__ dis, uint4* __restrict__ out, int n) {
    int lane = threadIdx.x & 31;
    int q = lane >> 3;
    int sub = lane & 7;
    int node = ((blockIdx.x * 256 + threadIdx.x) >> 5) * 4 + q;
    if (node >= n) return;
    int start = rowptr[node], d = deg[node];
    int dm = min(d, 8);
    int uidx = (sub < dm) ? csr[start + sub] : 0;
    int u[8];
#pragma unroll
    for (int j = 0; j < 8; j++) u[j] = __shfl_sync(FULLMASK, uidx, (q << 3) + j);
    float dn = dis[node];
    float a[8];
    {
        float4 s0 = x[(size_t)node * 16 + sub * 2];
        float4 s1 = x[(size_t)node * 16 + sub * 2 + 1];
        a[0] = s0.x * dn; a[1] = s0.y * dn; a[2] = s0.z * dn; a[3] = s0.w * dn;
        a[4] = s1.x * dn; a[5] = s1.y * dn; a[6] = s1.z * dn; a[7] = s1.w * dn;
    }
#pragma unroll
    for (int j = 0; j < 8; j++) {
        if (j < dm) {
            float du = dis[u[j]];
            float4 r0 = x[(size_t)u[j] * 16 + sub * 2];
            float4 r1 = x[(size_t)u[j] * 16 + sub * 2 + 1];
            a[0] += r0.x * du; a[1] += r0.y * du; a[2] += r0.z * du; a[3] += r0.w * du;
            a[4] += r1.x * du; a[5] += r1.y * du; a[6] += r1.z * du; a[7] += r1.w * du;
        }
    }
    for (int e = 8; e < d; e++) {
        int uu = csr[start + e];
        float du = dis[uu];
        float4 r0 = x[(size_t)uu * 16 + sub * 2];
        float4 r1 = x[(size_t)uu * 16 + sub * 2 + 1];
        a[0] += r0.x * du; a[1] += r0.y * du; a[2] += r0.z * du; a[3] += r0.w * du;
        a[4] += r1.x * du; a[5] += r1.y * du; a[6] += r1.z * du; a[7] += r1.w * du;
    }
    uint4 pk;
    pk.x = pack_bf2(a[0] * dn, a[1] * dn);
    pk.y = pack_bf2(a[2] * dn, a[3] * dn);
    pk.z = pack_bf2(a[4] * dn, a[5] * dn);
    pk.w = pack_bf2(a[6] * dn, a[7] * dn);
    out[(size_t)node * 8 + sub] = pk;
}

// ---------------- gather 128ch bf16, PACKED HADD2 accumulation ----------------
__global__ __launch_bounds__(256) void gather128bf_kernel(
    const int* __restrict__ rowptr, const int* __restrict__ deg,
    const int* __restrict__ csr, const __nv_bfloat16* __restrict__ hb,
    const float* __restrict__ dis, uint4* __restrict__ out, int n) {
    int lane = threadIdx.x & 31;
    int q = lane >> 3;
    int sub = lane & 7;
    int node = ((blockIdx.x * 256 + threadIdx.x) >> 5) * 4 + q;
    if (node >= n) return;
    const uint4* h16 = (const uint4*)hb;
    int start = rowptr[node], d = deg[node];
    int dm = min(d, 8);
    int uidx = (sub < dm) ? csr[start + sub] : 0;
    int u[8];
#pragma unroll
    for (int j = 0; j < 8; j++) u[j] = __shfl_sync(FULLMASK, uidx, (q << 3) + j);
    unsigned acc[8];
    {
        uint4 r0 = h16[(size_t)node * 16 + sub];
        uint4 r1 = h16[(size_t)node * 16 + 8 + sub];
        acc[0] = r0.x; acc[1] = r0.y; acc[2] = r0.z; acc[3] = r0.w;
        acc[4] = r1.x; acc[5] = r1.y; acc[6] = r1.z; acc[7] = r1.w;
    }
#pragma unroll
    for (int j = 0; j < 8; j++) {
        if (j < dm) {
            uint4 r0 = h16[(size_t)u[j] * 16 + sub];
            uint4 r1 = h16[(size_t)u[j] * 16 + 8 + sub];
            acc[0] = hadd2u(acc[0], r0.x); acc[1] = hadd2u(acc[1], r0.y);
            acc[2] = hadd2u(acc[2], r0.z); acc[3] = hadd2u(acc[3], r0.w);
            acc[4] = hadd2u(acc[4], r1.x); acc[5] = hadd2u(acc[5], r1.y);
            acc[6] = hadd2u(acc[6], r1.z); acc[7] = hadd2u(acc[7], r1.w);
        }
    }
    for (int e = 8; e < d; e++) {
        int uu = csr[start + e];
        uint4 r0 = h16[(size_t)uu * 16 + sub];
        uint4 r1 = h16[(size_t)uu * 16 + 8 + sub];
        acc[0] = hadd2u(acc[0], r0.x); acc[1] = hadd2u(acc[1], r0.y);
        acc[2] = hadd2u(acc[2], r0.z); acc[3] = hadd2u(acc[3], r0.w);
        acc[4] = hadd2u(acc[4], r1.x); acc[5] = hadd2u(acc[5], r1.y);
        acc[6] = hadd2u(acc[6], r1.z); acc[7] = hadd2u(acc[7], r1.w);
    }
    float dn = dis[node];
    uint4 pk0, pk1;
    {
        float2 f0 = unpack_bf2(acc[0]), f1 = unpack_bf2(acc[1]);
        float2 f2 = unpack_bf2(acc[2]), f3 = unpack_bf2(acc[3]);
        float2 g0 = unpack_bf2(acc[4]), g1 = unpack_bf2(acc[5]);
        float2 g2 = unpack_bf2(acc[6]), g3 = unpack_bf2(acc[7]);
        pk0.x = pack_bf2(f0.x * dn, f0.y * dn);
        pk0.y = pack_bf2(f1.x * dn, f1.y * dn);
        pk0.z = pack_bf2(f2.x * dn, f2.y * dn);
        pk0.w = pack_bf2(f3.x * dn, f3.y * dn);
        pk1.x = pack_bf2(g0.x * dn, g0.y * dn);
        pk1.y = pack_bf2(g1.x * dn, g1.y * dn);
        pk1.z = pack_bf2(g2.x * dn, g2.y * dn);
        pk1.w = pack_bf2(g3.x * dn, g3.y * dn);
    }
    out[(size_t)node * 16 + sub] = pk0;
    out[(size_t)node * 16 + 8 + sub] = pk1;
}

// ---------------- FCG gather with assemble fused ------------------------------
static __device__ __forceinline__ float4 fcg_row(
    const float4* __restrict__ pool4, const float4* __restrict__ emb4,
    const int* __restrict__ src, const int* __restrict__ isext, int i, int lane) {
    int s = src[i];
    if (isext[i] == 1) {
        int k = min(max(s, 0), VOCAB - 1);
        return emb4[(size_t)k * 32 + lane];
    } else {
        int k = min(max(s, 0), N_FUNC - 1);
        return pool4[(size_t)k * 32 + lane];
    }
}
__global__ __launch_bounds__(256) void gather128a_kernel(
    const int* __restrict__ rowptr, const int* __restrict__ deg,
    const int* __restrict__ csr,
    const float* __restrict__ pool, const float* __restrict__ emb,
    const int* __restrict__ src, const int* __restrict__ isext,
    const float* __restrict__ dis, float* __restrict__ out, int n) {
    int node = (blockIdx.x * 256 + threadIdx.x) >> 5;
    int lane = threadIdx.x & 31;
    if (node >= n) return;
    const float4* pool4 = (const float4*)pool;
    const float4* emb4 = (const float4*)emb;
    int start = rowptr[node], d = deg[node];
    int dm = min(d, 32);
    int uidx = (lane < dm) ? csr[start + lane] : 0;
    float dn = dis[node];
    float4 acc = fcg_row(pool4, emb4, src, isext, node, lane);
    acc.x *= dn; acc.y *= dn; acc.z *= dn; acc.w *= dn;
    for (int e = 0; e < dm; e++) {
        int u = __shfl_sync(FULLMASK, uidx, e);
        float du = dis[u];
        float4 v = fcg_row(pool4, emb4, src, isext, u, lane);
        acc.x += v.x * du; acc.y += v.y * du;
        acc.z += v.z * du; acc.w += v.w * du;
    }
    for (int e = 32; e < d; e++) {
        int u = csr[start + e];
        float du = dis[u];
        float4 v = fcg_row(pool4, emb4, src, isext, u, lane);
        acc.x += v.x * du; acc.y += v.y * du;
        acc.z += v.z * du; acc.w += v.w * du;
    }
    acc.x *= dn; acc.y *= dn; acc.z *= dn; acc.w *= dn;
    ((float4*)out)[(size_t)node * 32 + lane] = acc;
}

// ---------------- function-level mean pool (bf16 input) -----------------------
__global__ __launch_bounds__(256) void poolsegbf_kernel(
    const __nv_bfloat16* __restrict__ x, const int* __restrict__ start,
    float* __restrict__ pool, int nseg) {
    int f = (blockIdx.x * 256 + threadIdx.x) >> 5;
    int lane = threadIdx.x & 31;
    if (f >= nseg) return;
    int s = start[f], e = start[f + 1];
    const uint2* x8 = (const uint2*)x;
    float a0 = 0.f, a1 = 0.f, a2 = 0.f, a3 = 0.f;
    for (int i = s; i < e; i++) {
        uint2 raw = x8[(size_t)i * 32 + lane];
        float2 f0 = unpack_bf2(raw.x), f1 = unpack_bf2(raw.y);
        a0 += f0.x; a1 += f0.y; a2 += f1.x; a3 += f1.y;
    }
    float inv = 1.0f / (float)max(e - s, 1);
    ((float4*)pool)[(size_t)f * 32 + lane] = make_float4(a0 * inv, a1 * inv, a2 * inv, a3 * inv);
}

__global__ __launch_bounds__(128) void gpool_kernel(
    const float* __restrict__ y, const int* __restrict__ start, float* __restrict__ g) {
    int b = blockIdx.x, col = threadIdx.x;
    int s = start[b], e = start[b + 1];
    float acc = 0.f;
    for (int i = s; i < e; i++) acc += y[(size_t)i * 128 + col];
    g[b * 128 + col] = acc / (float)max(e - s, 1);
}

__global__ __launch_bounds__(256) void head_kernel(
    const float* __restrict__ g,
    const float* __restrict__ Wp1, const float* __restrict__ bp1,
    const float* __restrict__ Wp2, const float* __restrict__ bp2,
    const float* __restrict__ Wp3, const float* __restrict__ bp3,
    float* __restrict__ out) {
    __shared__ float G[NB * 128], H1[NB * 64], H2[NB * 32];
    int t = threadIdx.x;
    for (int i = t; i < NB * 128; i += 256) G[i] = g[i];
    __syncthreads();
    for (int i = t; i < NB * 64; i += 256) {
        int r = i >> 6, c = i & 63;
        float a = bp1[c];
        for (int k = 0; k < 128; k++) a += G[r * 128 + k] * Wp1[k * 64 + c];
        H1[i] = fmaxf(a, 0.f);
    }
    __syncthreads();
    for (int i = t; i < NB * 32; i += 256) {
        int r = i >> 5, c = i & 31;
        float a = bp2[c];
        for (int k = 0; k < 64; k++) a += H1[r * 64 + k] * Wp2[k * 32 + c];
        H2[i] = fmaxf(a, 0.f);
    }
    __syncthreads();
    if (t < NB) {
        float a = bp3[0];
        for (int k = 0; k < 32; k++) a += H2[t * 32 + k] * Wp3[k];
        out[t] = 1.0f / (1.0f + expf(-a));
    }
}

// ---------------- launch ----------------------------------------------------
extern "C" void kernel_launch(void* const* d_in, const int* in_sizes, int n_in,
                              void* d_out, int out_size) {
    const float* cfg_x  = (const float*)d_in[0];
    const int*   cfg_ei = (const int*)  d_in[1];
    const int*   n2f    = (const int*)  d_in[2];
    const int*   fcg_ei = (const int*)  d_in[3];
    const int*   fbatch = (const int*)  d_in[4];
    const int*   fsrc   = (const int*)  d_in[5];
    const int*   fext   = (const int*)  d_in[6];
    const float* W1  = (const float*)d_in[7];
    const float* b1  = (const float*)d_in[8];
    const float* W2  = (const float*)d_in[9];
    const float* b2  = (const float*)d_in[10];
    const float* emb = (const float*)d_in[11];
    const float* Wf  = (const float*)d_in[12];
    const float* bf  = (const float*)d_in[13];
    const float* Wp1 = (const float*)d_in[14];
    const float* bp1 = (const float*)d_in[15];
    const float* Wp2 = (const float*)d_in[16];
    const float* bp2 = (const float*)d_in[17];
    const float* Wp3 = (const float*)d_in[18];
    const float* bp3 = (const float*)d_in[19];
    float* out = (float*)d_out;

    void *p;
    cudaGetSymbolAddress(&p, g_b);       float* Bb     = (float*)p;
    cudaGetSymbolAddress(&p, g_hb);      __nv_bfloat16* HB = (__nv_bfloat16*)p;
    cudaGetSymbolAddress(&p, g_wb1);     __nv_bfloat16* Wb1 = (__nv_bfloat16*)p;
    cudaGetSymbolAddress(&p, g_wb2);     __nv_bfloat16* Wb2 = (__nv_bfloat16*)p;
    cudaGetSymbolAddress(&p, g_deg);     int*   deg    = (int*)p;
    cudaGetSymbolAddress(&p, g_dis);     float* dis    = (float*)p;
    cudaGetSymbolAddress(&p, g_rowptr);  int*   rowptr = (int*)p;
    cudaGetSymbolAddress(&p, g_csr);     int*   csr    = (int*)p;
    cudaGetSymbolAddress(&p, g_fdeg);    int*   fdeg   = (int*)p;
    cudaGetSymbolAddress(&p, g_fdis);    float* fdis   = (float*)p;
    cudaGetSymbolAddress(&p, g_frowptr); int*   frowptr= (int*)p;
    cudaGetSymbolAddress(&p, g_fcsr);    int*   fcsr   = (int*)p;
    cudaGetSymbolAddress(&p, g_fstart);  int*   fstart = (int*)p;
    cudaGetSymbolAddress(&p, g_bstart);  int*   bstart = (int*)p;
    cudaGetSymbolAddress(&p, g_pool);    float* pool   = (float*)p;
    cudaGetSymbolAddress(&p, g_fz);      float* fz     = (float*)p;
    cudaGetSymbolAddress(&p, g_fy);      float* fy     = (float*)p;
    cudaGetSymbolAddress(&p, g_g);       float* gg     = (float*)p;

    unsigned* z1b = (unsigned*)Bb;                   // gather1 out, 64ch bf16
    uint4*    z2b = (uint4*)Bb + (size_t)N_CFG * 8;  // gather2 out, 128ch bf16

    // dynamic smem sizes for full-stage GEMMs
    const int SM1 = 128 * (64 + 8) * 2 + 64 * 136 * 2 + 8 * 320 * 4 + 128 * 4;    // 46592
    const int SM2 = 128 * (128 + 8) * 2 + 128 * 136 * 2 + 8 * 320 * 4 + 128 * 4;  // 80384
    cudaFuncSetAttribute(gemmw_kernel<64, true, true>,
                         cudaFuncAttributeMaxDynamicSharedMemorySize, SM1);
    cudaFuncSetAttribute(gemmw_kernel<128, false, true>,
                         cudaFuncAttributeMaxDynamicSharedMemorySize, SM2);

    // prolog: init + degrees (dis fused into scan)
    init_kernel<<<(N_CFG + 255) / 256, 256>>>(W1, W2);
    deg_all_kernel<<<(E_CFG + E_FCG + 255) / 256, 256>>>(cfg_ei, fcg_ei);

    // CSR build (merged; dis in scan_local; bounds in scan_add)
    scan_local_all<<<NBLK_CFG + NBLK_FCG, 256>>>();
    scan_bsum_all<<<2, 512>>>();
    scan_add_all<<<(N_CFG + N_FCG + N_FUNC + NB + 2 + 255) / 256, 256>>>(n2f, fbatch);
    fill_csr_all<<<(E_CFG + E_FCG + 255) / 256, 256>>>(cfg_ei, fcg_ei);

    // CFG layer 1 (direct fp32 gather, tobf fused)
    gather64f_kernel<<<(N_CFG + 31) / 32, 256>>>(rowptr, deg, csr,
                                                 (const float4*)cfg_x, dis, (uint4*)z1b, N_CFG);
    gemmw_kernel<64, true, true><<<N_CFG / 128, 256, SM1>>>(
        (const __nv_bfloat16*)z1b, Wb1, b1, dis, nullptr, HB, N_CFG);

    // CFG layer 2 (packed bf16 HADD2 accumulation in gather)
    gather128bf_kernel<<<(N_CFG + 31) / 32, 256>>>(rowptr, deg, csr, HB, dis, z2b, N_CFG);
    gemmw_kernel<128, false, true><<<N_CFG / 128, 256, SM2>>>(
        (const __nv_bfloat16*)z2b, Wb2, b2, dis, nullptr, HB, N_CFG);

    // function-level mean pool (bf16 input)
    poolsegbf_kernel<<<(N_FUNC * 32 + 255) / 256, 256>>>(HB, fstart, pool, N_FUNC);

    // FCG layer (assemble fused into gather)
    gather128a_kernel<<<(N_FCG * 32 + 255) / 256, 256>>>(
        frowptr, fdeg, fcsr, pool, emb, fsrc, fext, fdis, fz, N_FCG);
    gemmx_kernel<128, false><<<(N_FCG + 127) / 128, 256>>>(fz, Wf, bf, fdis, fy, N_FCG);

    // binary-level mean pool + head
    gpool_kernel<<<NB, 128>>>(fy, bstart, gg);
    head_kernel<<<1, 256>>>(gg, Wp1, bp1, Wp2, bp2, Wp3, bp3, out);
}